// round 10
// baseline (speedup 1.0000x reference)
#include <cuda_runtime.h>
#include <cuda_bf16.h>
#include <cstdint>

#define Bn 256
#define Sn 2048
#define Tn 32
#define NCH 64
#define FULLMASK 0xffffffffu
#define LOG32F 3.4657359027997265f

// Scratch (device globals are the sanctioned scratch mechanism)
__device__ unsigned char g_hist[(size_t)Bn * (Sn - 1) * Tn];  // backpointers
__device__ unsigned char g_map[Bn][NCH][Tn];                  // chunk tag maps
__device__ unsigned char g_ent[Bn][NCH];                      // chunk entry tags
__device__ float g_den[Bn];
__device__ float g_num[Bn];
__device__ int   g_last[Bn];

// ---- packed f32x2 helpers (Blackwell) -------------------------------------
__device__ __forceinline__ float2 fadd2(float2 a, float2 b) {
    union { float2 f; unsigned long long u; } A, B, R;
    A.f = a; B.f = b;
    asm("add.rn.f32x2 %0, %1, %2;" : "=l"(R.u) : "l"(A.u), "l"(B.u));
    return R.f;
}
__device__ __forceinline__ float2 ffma2(float2 a, float2 b, float2 c) {
    union { float2 f; unsigned long long u; } A, B, C, R;
    A.f = a; B.f = b; C.f = c;
    asm("fma.rn.f32x2 %0, %1, %2, %3;" : "=l"(R.u) : "l"(A.u), "l"(B.u), "l"(C.u));
    return R.f;
}

// ---------------------------------------------------------------------------
// Forward algorithm, linear domain with deferred renorm.
// em via 8-deep per-lane register rotation (static slots via full unroll);
// exp(em) computed 4 iterations ahead of use (off the dependency chain).
// ---------------------------------------------------------------------------
template<bool AM>
__device__ __forceinline__ void fwd_loop(const float* __restrict__ em, int j,
                                         float* __restrict__ bufw,
                                         const signed char* __restrict__ mk,
                                         const float* __restrict__ startv,
                                         const float* __restrict__ endv,
                                         const float* __restrict__ trans,
                                         int b)
{
    float2 tc2[16];
    #pragma unroll
    for (int k = 0; k < 16; ++k) {
        float2 p;
        p.x = __expf(trans[(2 * k + 0) * Tn + j]) * 0.03125f;
        p.y = __expf(trans[(2 * k + 1) * Tn + j]) * 0.03125f;
        tc2[k] = p;
    }

    float raw[8], ee[8];
    #pragma unroll
    for (int p = 1; p <= 8; ++p) raw[p & 7] = em[(size_t)p * Tn + j];
    #pragma unroll
    for (int p = 1; p <= 4; ++p) ee[p] = __expf(raw[p]);

    float s  = __expf(startv[j] + em[j]);
    float Lr = 0.f;
    int   nm = 0;

    auto step = [&](int t, int sl, int sl4) {
        float* sb = bufw + (t & 1) * 32;
        sb[j] = s;
        __syncwarp();

        float2 a0 = make_float2(0.f, 0.f), a1 = make_float2(0.f, 0.f);
        float2 a2 = make_float2(0.f, 0.f), a3 = make_float2(0.f, 0.f);
        #pragma unroll
        for (int k = 0; k < 4; ++k) {
            const float4 qa = *(const float4*)(sb + 8 * k);
            const float4 qb = *(const float4*)(sb + 8 * k + 4);
            a0 = ffma2(make_float2(qa.x, qa.y), tc2[4 * k + 0], a0);
            a1 = ffma2(make_float2(qa.z, qa.w), tc2[4 * k + 1], a1);
            a2 = ffma2(make_float2(qb.x, qb.y), tc2[4 * k + 2], a2);
            a3 = ffma2(make_float2(qb.z, qb.w), tc2[4 * k + 3], a3);
        }
        const float2 a01 = fadd2(a0, a1);
        const float2 a23 = fadd2(a2, a3);
        const float2 aa  = fadd2(a01, a23);
        const float ns = (aa.x + aa.y) * ee[sl];
        if (AM) {
            s = ns;
        } else {
            const int m_ = mk[t];
            s = m_ ? ns : s;
            nm += (m_ != 0);
        }

        // schedule ahead: exp for step t+4, load for step t+8 (clamped tail)
        ee[sl4] = __expf(raw[sl4]);
        const int tl = (t + 8 < Sn) ? (t + 8) : (Sn - 1);
        raw[sl] = em[(size_t)tl * Tn + j];

        if ((t & 15) == 15) {                           // amortized renorm
            const float r  = __shfl_sync(FULLMASK, s, 0);
            const float rr = __frcp_rn(r);
            s *= rr;
            Lr -= __logf(rr);
        }
    };

    for (int tb = 1; tb + 7 < Sn; tb += 8) {
        #pragma unroll
        for (int u = 0; u < 8; ++u) step(tb + u, (u + 1) & 7, (u + 5) & 7);
    }
    #pragma unroll
    for (int u = 0; u < 7; ++u) step(Sn - 7 + u, (u + 1) & 7, (u + 5) & 7);

    if (AM) nm = Sn - 1;
    float v = s * __expf(endv[j]);
    #pragma unroll
    for (int off = 16; off; off >>= 1)
        v += __shfl_xor_sync(FULLMASK, v, off);
    if (j == 0) g_den[b] = (float)nm * LOG32F + Lr + __logf(v);
}

// ---------------------------------------------------------------------------
// Viterbi: pair-max + FMNMX tree (bit-exact value). First-occurrence argmax:
// descending scan for the first pair achieving the max, then the within-pair
// winner is recomputed from SMEM (vb + sTrans) off the critical path.
// em via 8-deep register rotation.
// ---------------------------------------------------------------------------
template<bool AM>
__device__ __forceinline__ void vit_loop(const float* __restrict__ em, int j,
                                         float* __restrict__ bufw,
                                         const signed char* __restrict__ mk,
                                         const float* __restrict__ sTrans,
                                         const float* __restrict__ startv,
                                         const float* __restrict__ endv,
                                         const float* __restrict__ trans,
                                         int b)
{
    float2 tc2[16];
    #pragma unroll
    for (int k = 0; k < 16; ++k) {
        float2 p;
        p.x = trans[(2 * k + 0) * Tn + j];
        p.y = trans[(2 * k + 1) * Tn + j];
        tc2[k] = p;
    }

    float raw[8];
    #pragma unroll
    for (int p = 1; p <= 8; ++p) raw[p & 7] = em[(size_t)p * Tn + j];

    float v = startv[j] + em[j];
    unsigned char* hb = g_hist + (size_t)b * (Sn - 1) * Tn;

    auto step = [&](int t, int sl) {
        float* vb = bufw + (t & 1) * 32;
        vb[j] = v;
        __syncwarp();
        const float emt = raw[sl];

        float tv[16];
        #pragma unroll
        for (int k = 0; k < 8; ++k) {
            const float4 q = *(const float4*)(vb + 4 * k);
            const float2 pa = fadd2(make_float2(q.x, q.y), tc2[2 * k + 0]);
            const float2 pb = fadd2(make_float2(q.z, q.w), tc2[2 * k + 1]);
            tv[2 * k + 0] = fmaxf(pa.x, pa.y);
            tv[2 * k + 1] = fmaxf(pb.x, pb.y);
        }
        // value tree (order-independent, bit-exact)
        float u0 = fmaxf(tv[0], tv[1]),  u1 = fmaxf(tv[2], tv[3]);
        float u2 = fmaxf(tv[4], tv[5]),  u3 = fmaxf(tv[6], tv[7]);
        float u4 = fmaxf(tv[8], tv[9]),  u5 = fmaxf(tv[10], tv[11]);
        float u6 = fmaxf(tv[12], tv[13]), u7 = fmaxf(tv[14], tv[15]);
        float w0 = fmaxf(u0, u1), w1 = fmaxf(u2, u3);
        float w2 = fmaxf(u4, u5), w3 = fmaxf(u6, u7);
        const float m = fmaxf(fmaxf(w0, w1), fmaxf(w2, w3));

        // first pair index with pair-max == m (descending scan, off-chain)
        int p = 15;
        #pragma unroll
        for (int i = 14; i >= 0; --i)
            p = (tv[i] == m) ? i : p;
        // within-pair winner recomputed from SMEM (conflict-free gathers)
        const float ca = vb[2 * p]     + sTrans[(2 * p) * Tn + j];
        const float cb = vb[2 * p + 1] + sTrans[(2 * p + 1) * Tn + j];
        const int bi = 2 * p + ((cb > ca) ? 1 : 0);

        const float nv = m + emt;
        if (AM) {
            v = nv;
            hb[(size_t)(t - 1) * Tn + j] = (unsigned char)bi;
        } else {
            const int m_ = mk[t];
            const int bp = m_ ? bi : j;
            v = m_ ? nv : v;
            hb[(size_t)(t - 1) * Tn + j] = (unsigned char)bp;
        }

        const int tl = (t + 8 < Sn) ? (t + 8) : (Sn - 1);
        raw[sl] = em[(size_t)tl * Tn + j];
    };

    for (int tb = 1; tb + 7 < Sn; tb += 8) {
        #pragma unroll
        for (int u = 0; u < 8; ++u) step(tb + u, (u + 1) & 7);
    }
    #pragma unroll
    for (int u = 0; u < 7; ++u) step(Sn - 7 + u, (u + 1) & 7);

    // last_tag = argmax_j (v_j + end_j), lowest index on ties
    float bv = v + endv[j];
    int   bidx = j;
    #pragma unroll
    for (int off = 16; off; off >>= 1) {
        const float ov = __shfl_xor_sync(FULLMASK, bv, off);
        const int   oi = __shfl_xor_sync(FULLMASK, bidx, off);
        const bool take = (ov > bv) || (ov == bv && oi < bidx);
        bv   = take ? ov : bv;
        bidx = take ? oi : bidx;
    }
    if (j == 0) g_last[b] = bidx;
}

// ---------------------------------------------------------------------------
// Main kernel: 128 CTAs x 128 threads, wave-1 (1 CTA/SM), 1 long warp/SMSP:
//   wid 0: fwd  batch 2*bid      wid 1: fwd  batch 2*bid+1
//   wid 2: vit  batch 2*bid      wid 3: vit  batch 2*bid+1
// ---------------------------------------------------------------------------
__global__ __launch_bounds__(128)
void crf_main_kernel(const float* __restrict__ pred,
                     const int*   __restrict__ amask,
                     const float* __restrict__ startv,
                     const float* __restrict__ endv,
                     const float* __restrict__ trans)
{
    const int wib = threadIdx.x >> 5;
    const int j   = threadIdx.x & 31;
    const int wb  = wib & 1;                 // which of the 2 batches
    const int b   = (blockIdx.x << 1) | wb;

    __shared__ __align__(16) float buf[4][2][32];
    __shared__ __align__(16) float sTrans[Tn * Tn];
    __shared__ signed char mkS[2][Sn];
    __shared__ int s_allones[2];

    if (wib < 2) {
        // mask load + all-ones detect (one warp per batch)
        const int* am = amask + (size_t)b * Sn;
        int okv = 1;
        for (int t = j; t < Sn; t += 32) {
            const int mv = am[t];
            mkS[wb][t] = (signed char)mv;
            okv &= (mv == 1);
        }
        const bool ao = __all_sync(FULLMASK, okv != 0);
        if (j == 0) s_allones[wb] = ao ? 1 : 0;
    } else {
        // trans tile: warps 2,3 load 16 rows each
        const int r0 = (wib - 2) * 16;
        #pragma unroll
        for (int k = 0; k < 16; ++k)
            sTrans[(r0 + k) * Tn + j] = trans[(r0 + k) * Tn + j];
    }
    __syncthreads();

    const float* em = pred + (size_t)b * Sn * Tn;
    float* bufw = &buf[wib][0][0];

    if (wib < 2) {
        if (s_allones[wb])
            fwd_loop<true >(em, j, bufw, mkS[wb], startv, endv, trans, b);
        else
            fwd_loop<false>(em, j, bufw, mkS[wb], startv, endv, trans, b);
    } else {
        if (s_allones[wb])
            vit_loop<true >(em, j, bufw, mkS[wb], sTrans, startv, endv, trans, b);
        else
            vit_loop<false>(em, j, bufw, mkS[wb], sTrans, startv, endv, trans, b);
    }
}

// ---------------------------------------------------------------------------
// Backtrace phase 1 (+ numerator blocks): blocks 0..1023 compute per-chunk
// tag maps; blocks 1024..1087 compute the numerator (4 batches each).
// ---------------------------------------------------------------------------
__global__ __launch_bounds__(128)
void bt_phase1(const float* __restrict__ pred,
               const int*   __restrict__ amask,
               const int*   __restrict__ labels,
               const float* __restrict__ startv,
               const float* __restrict__ endv,
               const float* __restrict__ trans)
{
    const int wib  = threadIdx.x >> 5;
    const int lane = threadIdx.x & 31;

    if (blockIdx.x >= (Bn * NCH) / 4) {
        // ------- Numerator: one warp per batch ------------------------------
        const int b = ((int)blockIdx.x - (Bn * NCH) / 4) * 4 + wib;
        const float* em = pred + (size_t)b * Sn * Tn;
        const int* lab = labels + (size_t)b * Sn;
        const int* am  = amask  + (size_t)b * Sn;
        float sum = 0.f;
        int   msum = 0;
        for (int t = lane; t < Sn; t += 32) {
            const int mt = am[t];
            msum += mt;
            const int tg = lab[t];
            if (t == 0) {
                sum += startv[tg] + em[tg];
            } else {
                const int tp = lab[t - 1];
                sum += (trans[tp * Tn + tg] + em[(size_t)t * Tn + tg]) * (float)mt;
            }
        }
        #pragma unroll
        for (int off = 16; off; off >>= 1) {
            sum  += __shfl_xor_sync(FULLMASK, sum, off);
            msum += __shfl_xor_sync(FULLMASK, msum, off);
        }
        if (lane == 0) {
            const int se = msum - 1;
            const int lt = lab[se];
            g_num[b] = sum + endv[lt];
        }
        return;
    }

    const int gw = (blockIdx.x << 2) | wib;       // 0 .. Bn*NCH-1
    const int b = gw >> 6;
    const int c = gw & 63;
    const int lo = c * 32;
    int hi = lo + 31; if (hi > Sn - 2) hi = Sn - 2;
    const int n = hi - lo + 1;

    __shared__ __align__(16) unsigned char sm[4][32 * Tn];
    unsigned char* S = sm[wib];
    const uint32_t* src = (const uint32_t*)(g_hist + ((size_t)b * (Sn - 1) + lo) * Tn);
    uint32_t* dst = (uint32_t*)S;
    for (int i = lane; i < n * 8; i += 32) dst[i] = src[i];
    __syncwarp();

    int tag = lane;
    for (int k = n - 1; k >= 0; --k) tag = S[k * Tn + tag];
    g_map[b][c][lane] = (unsigned char)tag;
}

// ---------------------------------------------------------------------------
// Backtrace phase 2: per batch, compose the 64 chunk maps from the top.
// ---------------------------------------------------------------------------
__global__ __launch_bounds__(128)
void bt_phase2(float* __restrict__ out)
{
    const int wib  = threadIdx.x >> 5;
    const int lane = threadIdx.x & 31;
    const int b = (blockIdx.x << 2) | wib;

    __shared__ __align__(16) unsigned char sm[4][NCH * Tn];
    __shared__ unsigned char se[4][NCH];
    unsigned char* S = sm[wib];
    const uint32_t* src = (const uint32_t*)&g_map[b][0][0];
    uint32_t* dst = (uint32_t*)S;
    for (int i = lane; i < NCH * Tn / 4; i += 32) dst[i] = src[i];
    __syncwarp();

    if (lane == 0) {
        int e = g_last[b];
        out[(size_t)b * Sn + (Sn - 1)] = (float)e;
        for (int c = NCH - 1; c >= 0; --c) {
            se[wib][c] = (unsigned char)e;   // entry tag for chunk c
            e = S[c * Tn + e];               // exit = map[entry]
        }
    }
    __syncwarp();
    for (int c = lane; c < NCH; c += 32) g_ent[b][c] = se[wib][c];
}

// ---------------------------------------------------------------------------
// Backtrace phase 3: re-chase each chunk from its entry tag; coalesced write.
// ---------------------------------------------------------------------------
__global__ __launch_bounds__(128)
void bt_phase3(float* __restrict__ out)
{
    const int wib  = threadIdx.x >> 5;
    const int lane = threadIdx.x & 31;
    const int gw = (blockIdx.x << 2) | wib;
    const int b = gw >> 6;
    const int c = gw & 63;
    const int lo = c * 32;
    int hi = lo + 31; if (hi > Sn - 2) hi = Sn - 2;
    const int n = hi - lo + 1;

    __shared__ __align__(16) unsigned char sm[4][32 * Tn];
    __shared__ unsigned char stag[4][32];
    unsigned char* S = sm[wib];
    const uint32_t* src = (const uint32_t*)(g_hist + ((size_t)b * (Sn - 1) + lo) * Tn);
    uint32_t* dst = (uint32_t*)S;
    for (int i = lane; i < n * 8; i += 32) dst[i] = src[i];
    __syncwarp();

    if (lane == 0) {
        int tag = g_ent[b][c];
        for (int k = n - 1; k >= 0; --k) {
            tag = S[k * Tn + tag];
            stag[wib][k] = (unsigned char)tag;
        }
    }
    __syncwarp();
    if (lane < n) out[(size_t)b * Sn + lo + lane] = (float)stag[wib][lane];
}

// ---------------------------------------------------------------------------
// Loss: -mean(num - den)
// ---------------------------------------------------------------------------
__global__ void crf_loss_kernel(float* __restrict__ out)
{
    __shared__ float red[Bn];
    const int t = threadIdx.x;
    red[t] = g_num[t] - g_den[t];
    __syncthreads();
    #pragma unroll
    for (int off = 128; off; off >>= 1) {
        if (t < off) red[t] += red[t + off];
        __syncthreads();
    }
    if (t == 0) out[(size_t)Bn * Sn] = -(red[0] / (float)Bn);
}

extern "C" void kernel_launch(void* const* d_in, const int* in_sizes, int n_in,
                              void* d_out, int out_size)
{
    const float* pred   = (const float*)d_in[0];
    const int*   amask  = (const int*)  d_in[1];
    const int*   labels = (const int*)  d_in[2];
    const float* startv = (const float*)d_in[3];
    const float* endv   = (const float*)d_in[4];
    const float* trans  = (const float*)d_in[5];
    float* out = (float*)d_out;

    crf_main_kernel<<<128, 128>>>(pred, amask, startv, endv, trans);
    bt_phase1<<<(Bn * NCH) / 4 + Bn / 4, 128>>>(pred, amask, labels, startv, endv, trans);
    bt_phase2<<<Bn / 4, 128>>>(out);
    bt_phase3<<<(Bn * NCH) / 4, 128>>>(out);
    crf_loss_kernel<<<1, Bn>>>(out);
}

// round 11
// speedup vs baseline: 1.0740x; 1.0740x over previous
#include <cuda_runtime.h>
#include <cuda_bf16.h>
#include <cstdint>

#define Bn 256
#define Sn 2048
#define Tn 32
#define NCH 64
#define FULLMASK 0xffffffffu
#define LOG32F 3.4657359027997265f

// Scratch (device globals are the sanctioned scratch mechanism)
__device__ unsigned char g_hist[(size_t)Bn * (Sn - 1) * Tn];  // backpointers
__device__ unsigned char g_map[Bn][NCH][Tn];                  // chunk tag maps
__device__ unsigned char g_ent[Bn][NCH];                      // chunk entry tags
__device__ float g_den[Bn];
__device__ float g_num[Bn];
__device__ int   g_last[Bn];

// ---- packed f32x2 helpers (Blackwell) -------------------------------------
__device__ __forceinline__ float2 fadd2(float2 a, float2 b) {
    union { float2 f; unsigned long long u; } A, B, R;
    A.f = a; B.f = b;
    asm("add.rn.f32x2 %0, %1, %2;" : "=l"(R.u) : "l"(A.u), "l"(B.u));
    return R.f;
}
__device__ __forceinline__ float2 ffma2(float2 a, float2 b, float2 c) {
    union { float2 f; unsigned long long u; } A, B, C, R;
    A.f = a; B.f = b; C.f = c;
    asm("fma.rn.f32x2 %0, %1, %2, %3;" : "=l"(R.u) : "l"(A.u), "l"(B.u), "l"(C.u));
    return R.f;
}

// ---- cp.async helpers ------------------------------------------------------
__device__ __forceinline__ uint32_t smem_u32(const void* p) {
    return (uint32_t)__cvta_generic_to_shared(p);
}
__device__ __forceinline__ void cp4(uint32_t d, const void* s) {
    asm volatile("cp.async.ca.shared.global [%0], [%1], 4;" :: "r"(d), "l"(s));
}
#define CP_COMMIT() asm volatile("cp.async.commit_group;")
#define CP_WAIT10() asm volatile("cp.async.wait_group 10;")

// prefetch ring: 16 stages, issue 12 ahead, wait leaves <=10 pending
#define RD 12

// ---------------------------------------------------------------------------
// Forward algorithm, linear domain with deferred renorm. em via cp.async ring.
// (identical to the round-7 verified version)
// ---------------------------------------------------------------------------
template<bool AM>
__device__ __forceinline__ void fwd_loop(const float* __restrict__ em, int j,
                                         float* __restrict__ bufw,
                                         float* __restrict__ ringw,
                                         const signed char* __restrict__ mk,
                                         const float* __restrict__ startv,
                                         const float* __restrict__ endv,
                                         const float* __restrict__ trans,
                                         int b)
{
    float2 tc2[16];
    #pragma unroll
    for (int k = 0; k < 16; ++k) {
        float2 p;
        p.x = __expf(trans[(2 * k + 0) * Tn + j]) * 0.03125f;
        p.y = __expf(trans[(2 * k + 1) * Tn + j]) * 0.03125f;
        tc2[k] = p;
    }

    const uint32_t rbase = smem_u32(ringw);
    #pragma unroll
    for (int p = 1; p <= RD; ++p) {
        cp4(rbase + (((p & 15) * 32 + j) << 2), em + (size_t)p * Tn + j);
        CP_COMMIT();
    }

    float s  = __expf(startv[j] + em[j]);
    float Lr = 0.f;
    int   nm = 0;

    #pragma unroll 2
    for (int t = 1; t < Sn; ++t) {
        CP_WAIT10();
        float* sb = bufw + (t & 1) * 32;
        sb[j] = s;
        __syncwarp();
        const float emv = ringw[(t & 15) * 32 + j];
        const float ee  = __expf(emv);

        float2 a0 = {0.f, 0.f}, a1 = {0.f, 0.f}, a2 = {0.f, 0.f}, a3 = {0.f, 0.f};
        #pragma unroll
        for (int k = 0; k < 4; ++k) {
            const float4 qa = *(const float4*)(sb + 8 * k);
            const float4 qb = *(const float4*)(sb + 8 * k + 4);
            a0 = ffma2(make_float2(qa.x, qa.y), tc2[4 * k + 0], a0);
            a1 = ffma2(make_float2(qa.z, qa.w), tc2[4 * k + 1], a1);
            a2 = ffma2(make_float2(qb.x, qb.y), tc2[4 * k + 2], a2);
            a3 = ffma2(make_float2(qb.z, qb.w), tc2[4 * k + 3], a3);
        }
        const float2 a01 = fadd2(a0, a1);
        const float2 a23 = fadd2(a2, a3);
        const float2 aa  = fadd2(a01, a23);
        const float ns = (aa.x + aa.y) * ee;
        if (AM) {
            s = ns;
        } else {
            const int m_ = mk[t];
            s = m_ ? ns : s;
            nm += (m_ != 0);
        }

        // refill ring (clamped tail keeps group accounting uniform)
        const int tf = t + RD;
        const int tc = tf < Sn - 1 ? tf : Sn - 1;
        cp4(rbase + ((((tf & 15) * 32) + j) << 2), em + (size_t)tc * Tn + j);
        CP_COMMIT();

        if ((t & 15) == 15) {                           // amortized renorm
            const float r  = __shfl_sync(FULLMASK, s, 0);
            const float rr = __frcp_rn(r);
            s *= rr;
            Lr -= __logf(rr);
        }
    }
    if (AM) nm = Sn - 1;
    float v = s * __expf(endv[j]);
    #pragma unroll
    for (int off = 16; off; off >>= 1)
        v += __shfl_xor_sync(FULLMASK, v, off);
    if (j == 0) g_den[b] = (float)nm * LOG32F + Lr + __logf(v);
}

// ---------------------------------------------------------------------------
// Viterbi, software-pipelined: value phase (gather -> pairs -> tree -> nv)
// commits the new state to SMEM + syncwarp IMMEDIATELY, then the argmax
// phase (scan + within-pair resolve via 2 dynamic SHFLs of vold + STG)
// executes after the sync, off the inter-step critical path.
// Arithmetic and tie semantics identical to the verified r4/r7 versions.
// ---------------------------------------------------------------------------
template<bool AM>
__device__ __forceinline__ void vit_loop(const float* __restrict__ em, int j,
                                         float* __restrict__ bufw,
                                         float* __restrict__ ringw,
                                         const signed char* __restrict__ mk,
                                         const float* __restrict__ sTrans,
                                         const float* __restrict__ startv,
                                         const float* __restrict__ endv,
                                         const float* __restrict__ trans,
                                         int b)
{
    float2 tc2[16];
    #pragma unroll
    for (int k = 0; k < 16; ++k) {
        float2 p;
        p.x = trans[(2 * k + 0) * Tn + j];
        p.y = trans[(2 * k + 1) * Tn + j];
        tc2[k] = p;
    }

    const uint32_t rbase = smem_u32(ringw);
    #pragma unroll
    for (int p = 1; p <= RD; ++p) {
        cp4(rbase + (((p & 15) * 32 + j) << 2), em + (size_t)p * Tn + j);
        CP_COMMIT();
    }

    float v = startv[j] + em[j];
    unsigned char* hb = g_hist + (size_t)b * (Sn - 1) * Tn;

    bufw[j] = v;                 // buf[0] holds state at t=0
    __syncwarp();

    #pragma unroll 2
    for (int t = 1; t < Sn; ++t) {
        CP_WAIT10();
        const float* vb = bufw + ((t - 1) & 1) * 32;

        float tv[16];
        #pragma unroll
        for (int k = 0; k < 8; ++k) {
            const float4 q = *(const float4*)(vb + 4 * k);
            const float2 pa = fadd2(make_float2(q.x, q.y), tc2[2 * k + 0]);
            const float2 pb = fadd2(make_float2(q.z, q.w), tc2[2 * k + 1]);
            tv[2 * k + 0] = fmaxf(pa.x, pa.y);
            tv[2 * k + 1] = fmaxf(pb.x, pb.y);
        }
        // value tree (order-independent, bit-exact)
        float u0 = fmaxf(tv[0], tv[1]),  u1 = fmaxf(tv[2], tv[3]);
        float u2 = fmaxf(tv[4], tv[5]),  u3 = fmaxf(tv[6], tv[7]);
        float u4 = fmaxf(tv[8], tv[9]),  u5 = fmaxf(tv[10], tv[11]);
        float u6 = fmaxf(tv[12], tv[13]), u7 = fmaxf(tv[14], tv[15]);
        float w0 = fmaxf(u0, u1), w1 = fmaxf(u2, u3);
        float w2 = fmaxf(u4, u5), w3 = fmaxf(u6, u7);
        const float m = fmaxf(fmaxf(w0, w1), fmaxf(w2, w3));

        const float emt = ringw[(t & 15) * 32 + j];
        const float nv  = m + emt;
        const float vold = v;
        int m_ = 1;
        if (AM) {
            v = nv;
        } else {
            m_ = mk[t];
            v = m_ ? nv : v;
        }

        bufw[(t & 1) * 32 + j] = v;      // commit next state EARLY
        __syncwarp();

        // ---- argmax phase (transition t), after the inter-step gate -------
        int p = 15;
        #pragma unroll
        for (int i = 14; i >= 0; --i)
            p = (tv[i] == m) ? i : p;
        // within-pair winner: identical values to vb[2p]/vb[2p+1] recompute
        const float ca = __shfl_sync(FULLMASK, vold, 2 * p + 0) + sTrans[(2 * p + 0) * Tn + j];
        const float cb = __shfl_sync(FULLMASK, vold, 2 * p + 1) + sTrans[(2 * p + 1) * Tn + j];
        const int bi = 2 * p + ((cb > ca) ? 1 : 0);
        const int bp = AM ? bi : (m_ ? bi : j);
        hb[(size_t)(t - 1) * Tn + j] = (unsigned char)bp;

        const int tf = t + RD;
        const int tcl = tf < Sn - 1 ? tf : Sn - 1;
        cp4(rbase + ((((tf & 15) * 32) + j) << 2), em + (size_t)tcl * Tn + j);
        CP_COMMIT();
    }
    // last_tag = argmax_j (v_j + end_j), lowest index on ties
    float bv = v + endv[j];
    int   bidx = j;
    #pragma unroll
    for (int off = 16; off; off >>= 1) {
        const float ov = __shfl_xor_sync(FULLMASK, bv, off);
        const int   oi = __shfl_xor_sync(FULLMASK, bidx, off);
        const bool take = (ov > bv) || (ov == bv && oi < bidx);
        bv   = take ? ov : bv;
        bidx = take ? oi : bidx;
    }
    if (j == 0) g_last[b] = bidx;
}

// ---------------------------------------------------------------------------
// Main kernel: 128 CTAs x 128 threads, wave-1 (1 CTA/SM), 1 long warp/SMSP:
//   wid 0: fwd  batch 2*bid      wid 1: fwd  batch 2*bid+1
//   wid 2: vit  batch 2*bid      wid 3: vit  batch 2*bid+1
// ---------------------------------------------------------------------------
__global__ __launch_bounds__(128)
void crf_main_kernel(const float* __restrict__ pred,
                     const int*   __restrict__ amask,
                     const float* __restrict__ startv,
                     const float* __restrict__ endv,
                     const float* __restrict__ trans)
{
    const int wib = threadIdx.x >> 5;
    const int j   = threadIdx.x & 31;
    const int wb  = wib & 1;                 // which of the 2 batches
    const int b   = (blockIdx.x << 1) | wb;

    __shared__ __align__(16) float ring[4][16][32];
    __shared__ __align__(16) float buf[4][2][32];
    __shared__ __align__(16) float sTrans[Tn * Tn];
    __shared__ signed char mkS[2][Sn];
    __shared__ int s_allones[2];

    if (wib < 2) {
        // mask load + all-ones detect (one warp per batch)
        const int* am = amask + (size_t)b * Sn;
        int okv = 1;
        for (int t = j; t < Sn; t += 32) {
            const int mv = am[t];
            mkS[wb][t] = (signed char)mv;
            okv &= (mv == 1);
        }
        const bool ao = __all_sync(FULLMASK, okv != 0);
        if (j == 0) s_allones[wb] = ao ? 1 : 0;
    } else {
        // trans tile: warps 2,3 load 16 rows each
        const int r0 = (wib - 2) * 16;
        #pragma unroll
        for (int k = 0; k < 16; ++k)
            sTrans[(r0 + k) * Tn + j] = trans[(r0 + k) * Tn + j];
    }
    __syncthreads();

    const float* em = pred + (size_t)b * Sn * Tn;
    float* bufw  = &buf[wib][0][0];
    float* ringw = &ring[wib][0][0];

    if (wib < 2) {
        if (s_allones[wb])
            fwd_loop<true >(em, j, bufw, ringw, mkS[wb], startv, endv, trans, b);
        else
            fwd_loop<false>(em, j, bufw, ringw, mkS[wb], startv, endv, trans, b);
    } else {
        if (s_allones[wb])
            vit_loop<true >(em, j, bufw, ringw, mkS[wb], sTrans, startv, endv, trans, b);
        else
            vit_loop<false>(em, j, bufw, ringw, mkS[wb], sTrans, startv, endv, trans, b);
    }
}

// ---------------------------------------------------------------------------
// Backtrace phase 1 (+ numerator blocks): blocks 0..1023 compute per-chunk
// tag maps; blocks 1024..1087 compute the numerator (4 batches each).
// ---------------------------------------------------------------------------
__global__ __launch_bounds__(128)
void bt_phase1(const float* __restrict__ pred,
               const int*   __restrict__ amask,
               const int*   __restrict__ labels,
               const float* __restrict__ startv,
               const float* __restrict__ endv,
               const float* __restrict__ trans)
{
    const int wib  = threadIdx.x >> 5;
    const int lane = threadIdx.x & 31;

    if (blockIdx.x >= (Bn * NCH) / 4) {
        // ------- Numerator: one warp per batch ------------------------------
        const int b = ((int)blockIdx.x - (Bn * NCH) / 4) * 4 + wib;
        const float* em = pred + (size_t)b * Sn * Tn;
        const int* lab = labels + (size_t)b * Sn;
        const int* am  = amask  + (size_t)b * Sn;
        float sum = 0.f;
        int   msum = 0;
        for (int t = lane; t < Sn; t += 32) {
            const int mt = am[t];
            msum += mt;
            const int tg = lab[t];
            if (t == 0) {
                sum += startv[tg] + em[tg];
            } else {
                const int tp = lab[t - 1];
                sum += (trans[tp * Tn + tg] + em[(size_t)t * Tn + tg]) * (float)mt;
            }
        }
        #pragma unroll
        for (int off = 16; off; off >>= 1) {
            sum  += __shfl_xor_sync(FULLMASK, sum, off);
            msum += __shfl_xor_sync(FULLMASK, msum, off);
        }
        if (lane == 0) {
            const int se = msum - 1;
            const int lt = lab[se];
            g_num[b] = sum + endv[lt];
        }
        return;
    }

    const int gw = (blockIdx.x << 2) | wib;       // 0 .. Bn*NCH-1
    const int b = gw >> 6;
    const int c = gw & 63;
    const int lo = c * 32;
    int hi = lo + 31; if (hi > Sn - 2) hi = Sn - 2;
    const int n = hi - lo + 1;

    __shared__ __align__(16) unsigned char sm[4][32 * Tn];
    unsigned char* S = sm[wib];
    const uint32_t* src = (const uint32_t*)(g_hist + ((size_t)b * (Sn - 1) + lo) * Tn);
    uint32_t* dst = (uint32_t*)S;
    for (int i = lane; i < n * 8; i += 32) dst[i] = src[i];
    __syncwarp();

    int tag = lane;
    for (int k = n - 1; k >= 0; --k) tag = S[k * Tn + tag];
    g_map[b][c][lane] = (unsigned char)tag;
}

// ---------------------------------------------------------------------------
// Backtrace phase 2: per batch, compose the 64 chunk maps from the top.
// ---------------------------------------------------------------------------
__global__ __launch_bounds__(128)
void bt_phase2(float* __restrict__ out)
{
    const int wib  = threadIdx.x >> 5;
    const int lane = threadIdx.x & 31;
    const int b = (blockIdx.x << 2) | wib;

    __shared__ __align__(16) unsigned char sm[4][NCH * Tn];
    __shared__ unsigned char se[4][NCH];
    unsigned char* S = sm[wib];
    const uint32_t* src = (const uint32_t*)&g_map[b][0][0];
    uint32_t* dst = (uint32_t*)S;
    for (int i = lane; i < NCH * Tn / 4; i += 32) dst[i] = src[i];
    __syncwarp();

    if (lane == 0) {
        int e = g_last[b];
        out[(size_t)b * Sn + (Sn - 1)] = (float)e;
        for (int c = NCH - 1; c >= 0; --c) {
            se[wib][c] = (unsigned char)e;   // entry tag for chunk c
            e = S[c * Tn + e];               // exit = map[entry]
        }
    }
    __syncwarp();
    for (int c = lane; c < NCH; c += 32) g_ent[b][c] = se[wib][c];
}

// ---------------------------------------------------------------------------
// Backtrace phase 3: re-chase each chunk from its entry tag; coalesced write.
// ---------------------------------------------------------------------------
__global__ __launch_bounds__(128)
void bt_phase3(float* __restrict__ out)
{
    const int wib  = threadIdx.x >> 5;
    const int lane = threadIdx.x & 31;
    const int gw = (blockIdx.x << 2) | wib;
    const int b = gw >> 6;
    const int c = gw & 63;
    const int lo = c * 32;
    int hi = lo + 31; if (hi > Sn - 2) hi = Sn - 2;
    const int n = hi - lo + 1;

    __shared__ __align__(16) unsigned char sm[4][32 * Tn];
    __shared__ unsigned char stag[4][32];
    unsigned char* S = sm[wib];
    const uint32_t* src = (const uint32_t*)(g_hist + ((size_t)b * (Sn - 1) + lo) * Tn);
    uint32_t* dst = (uint32_t*)S;
    for (int i = lane; i < n * 8; i += 32) dst[i] = src[i];
    __syncwarp();

    if (lane == 0) {
        int tag = g_ent[b][c];
        for (int k = n - 1; k >= 0; --k) {
            tag = S[k * Tn + tag];
            stag[wib][k] = (unsigned char)tag;
        }
    }
    __syncwarp();
    if (lane < n) out[(size_t)b * Sn + lo + lane] = (float)stag[wib][lane];
}

// ---------------------------------------------------------------------------
// Loss: -mean(num - den)
// ---------------------------------------------------------------------------
__global__ void crf_loss_kernel(float* __restrict__ out)
{
    __shared__ float red[Bn];
    const int t = threadIdx.x;
    red[t] = g_num[t] - g_den[t];
    __syncthreads();
    #pragma unroll
    for (int off = 128; off; off >>= 1) {
        if (t < off) red[t] += red[t + off];
        __syncthreads();
    }
    if (t == 0) out[(size_t)Bn * Sn] = -(red[0] / (float)Bn);
}

extern "C" void kernel_launch(void* const* d_in, const int* in_sizes, int n_in,
                              void* d_out, int out_size)
{
    const float* pred   = (const float*)d_in[0];
    const int*   amask  = (const int*)  d_in[1];
    const int*   labels = (const int*)  d_in[2];
    const float* startv = (const float*)d_in[3];
    const float* endv   = (const float*)d_in[4];
    const float* trans  = (const float*)d_in[5];
    float* out = (float*)d_out;

    crf_main_kernel<<<128, 128>>>(pred, amask, startv, endv, trans);
    bt_phase1<<<(Bn * NCH) / 4 + Bn / 4, 128>>>(pred, amask, labels, startv, endv, trans);
    bt_phase2<<<Bn / 4, 128>>>(out);
    bt_phase3<<<(Bn * NCH) / 4, 128>>>(out);
    crf_loss_kernel<<<1, Bn>>>(out);
}

// round 12
// speedup vs baseline: 1.2493x; 1.1632x over previous
#include <cuda_runtime.h>
#include <cuda_bf16.h>
#include <cstdint>

#define Bn 256
#define Sn 2048
#define Tn 32
#define NCH 64
#define FULLMASK 0xffffffffu
#define LOG32F 3.4657359027997265f

// Scratch (device globals are the sanctioned scratch mechanism)
__device__ unsigned char g_hist[(size_t)Bn * (Sn - 1) * Tn];  // backpointers
__device__ unsigned char g_map[Bn][NCH][Tn];                  // chunk tag maps
__device__ unsigned char g_ent[Bn][NCH];                      // chunk entry tags
__device__ float g_den[Bn];
__device__ float g_num[Bn];
__device__ int   g_last[Bn];

// ---- packed f32x2 helpers (Blackwell) -------------------------------------
__device__ __forceinline__ float2 fadd2(float2 a, float2 b) {
    union { float2 f; unsigned long long u; } A, B, R;
    A.f = a; B.f = b;
    asm("add.rn.f32x2 %0, %1, %2;" : "=l"(R.u) : "l"(A.u), "l"(B.u));
    return R.f;
}
__device__ __forceinline__ float2 ffma2(float2 a, float2 b, float2 c) {
    union { float2 f; unsigned long long u; } A, B, C, R;
    A.f = a; B.f = b; C.f = c;
    asm("fma.rn.f32x2 %0, %1, %2, %3;" : "=l"(R.u) : "l"(A.u), "l"(B.u), "l"(C.u));
    return R.f;
}

// ---- cp.async helpers ------------------------------------------------------
__device__ __forceinline__ uint32_t smem_u32(const void* p) {
    return (uint32_t)__cvta_generic_to_shared(p);
}
__device__ __forceinline__ void cp4(uint32_t d, const void* s) {
    asm volatile("cp.async.ca.shared.global [%0], [%1], 4;" :: "r"(d), "l"(s));
}
#define CP_COMMIT() asm volatile("cp.async.commit_group;")
#define CP_WAIT10() asm volatile("cp.async.wait_group 10;")

// prefetch ring: 16 stages, issue 12 ahead, wait leaves <=10 pending
#define RD 12

// ---------------------------------------------------------------------------
// Forward algorithm, linear domain with deferred renorm. em via cp.async ring.
// (identical to the round-7/11 verified version)
// ---------------------------------------------------------------------------
template<bool AM>
__device__ __forceinline__ void fwd_loop(const float* __restrict__ em, int j,
                                         float* __restrict__ bufw,
                                         float* __restrict__ ringw,
                                         const signed char* __restrict__ mk,
                                         const float* __restrict__ startv,
                                         const float* __restrict__ endv,
                                         const float* __restrict__ trans,
                                         int b)
{
    float2 tc2[16];
    #pragma unroll
    for (int k = 0; k < 16; ++k) {
        float2 p;
        p.x = __expf(trans[(2 * k + 0) * Tn + j]) * 0.03125f;
        p.y = __expf(trans[(2 * k + 1) * Tn + j]) * 0.03125f;
        tc2[k] = p;
    }

    const uint32_t rbase = smem_u32(ringw);
    #pragma unroll
    for (int p = 1; p <= RD; ++p) {
        cp4(rbase + (((p & 15) * 32 + j) << 2), em + (size_t)p * Tn + j);
        CP_COMMIT();
    }

    float s  = __expf(startv[j] + em[j]);
    float Lr = 0.f;
    int   nm = 0;

    #pragma unroll 4
    for (int t = 1; t < Sn; ++t) {
        CP_WAIT10();
        float* sb = bufw + (t & 1) * 32;
        sb[j] = s;
        __syncwarp();
        const float emv = ringw[(t & 15) * 32 + j];
        const float ee  = __expf(emv);

        float2 a0 = {0.f, 0.f}, a1 = {0.f, 0.f}, a2 = {0.f, 0.f}, a3 = {0.f, 0.f};
        #pragma unroll
        for (int k = 0; k < 4; ++k) {
            const float4 qa = *(const float4*)(sb + 8 * k);
            const float4 qb = *(const float4*)(sb + 8 * k + 4);
            a0 = ffma2(make_float2(qa.x, qa.y), tc2[4 * k + 0], a0);
            a1 = ffma2(make_float2(qa.z, qa.w), tc2[4 * k + 1], a1);
            a2 = ffma2(make_float2(qb.x, qb.y), tc2[4 * k + 2], a2);
            a3 = ffma2(make_float2(qb.z, qb.w), tc2[4 * k + 3], a3);
        }
        const float2 a01 = fadd2(a0, a1);
        const float2 a23 = fadd2(a2, a3);
        const float2 aa  = fadd2(a01, a23);
        const float ns = (aa.x + aa.y) * ee;
        if (AM) {
            s = ns;
        } else {
            const int m_ = mk[t];
            s = m_ ? ns : s;
            nm += (m_ != 0);
        }

        // refill ring (clamped tail keeps group accounting uniform)
        const int tf = t + RD;
        const int tc = tf < Sn - 1 ? tf : Sn - 1;
        cp4(rbase + ((((tf & 15) * 32) + j) << 2), em + (size_t)tc * Tn + j);
        CP_COMMIT();

        if ((t & 15) == 15) {                           // amortized renorm
            const float r  = __shfl_sync(FULLMASK, s, 0);
            const float rr = __frcp_rn(r);
            s *= rr;
            Lr -= __logf(rr);
        }
    }
    if (AM) nm = Sn - 1;
    float v = s * __expf(endv[j]);
    #pragma unroll
    for (int off = 16; off; off >>= 1)
        v += __shfl_xor_sync(FULLMASK, v, off);
    if (j == 0) g_den[b] = (float)nm * LOG32F + Lr + __logf(v);
}

// ---------------------------------------------------------------------------
// Viterbi with TOURNAMENT argmax: value and index merged at every tree level,
// left wins ties (strict '>' takes right) == first-occurrence jnp.argmax.
// No serial scan, no dynamic shfl/LDS -> dependent-latency chain is just the
// gather + 5-level tree; the 31 index selects overlap the value maxes (ILP).
// Verified-correct argmax structure from round 3; ring/exchange from round 4.
// ---------------------------------------------------------------------------
template<bool AM>
__device__ __forceinline__ void vit_loop(const float* __restrict__ em, int j,
                                         float* __restrict__ bufw,
                                         float* __restrict__ ringw,
                                         const signed char* __restrict__ mk,
                                         const float* __restrict__ startv,
                                         const float* __restrict__ endv,
                                         const float* __restrict__ trans,
                                         int b)
{
    float2 tc2[16];
    #pragma unroll
    for (int k = 0; k < 16; ++k) {
        float2 p;
        p.x = trans[(2 * k + 0) * Tn + j];
        p.y = trans[(2 * k + 1) * Tn + j];
        tc2[k] = p;
    }

    const uint32_t rbase = smem_u32(ringw);
    #pragma unroll
    for (int p = 1; p <= RD; ++p) {
        cp4(rbase + (((p & 15) * 32 + j) << 2), em + (size_t)p * Tn + j);
        CP_COMMIT();
    }

    float v = startv[j] + em[j];
    unsigned char* hb = g_hist + (size_t)b * (Sn - 1) * Tn;

    #pragma unroll 4
    for (int t = 1; t < Sn; ++t) {
        CP_WAIT10();
        float* vb = bufw + (t & 1) * 32;
        vb[j] = v;
        __syncwarp();
        const float emt = ringw[(t & 15) * 32 + j];

        // L1: 16 merged pairs (value + index), left-priority strict '>'
        float tv[16]; int ti[16];
        #pragma unroll
        for (int k = 0; k < 8; ++k) {
            const float4 q = *(const float4*)(vb + 4 * k);
            const float2 p0 = fadd2(make_float2(q.x, q.y), tc2[2 * k + 0]);
            const float2 p1 = fadd2(make_float2(q.z, q.w), tc2[2 * k + 1]);
            const bool s0 = p0.y > p0.x;
            tv[2 * k + 0] = fmaxf(p0.x, p0.y);
            ti[2 * k + 0] = s0 ? (4 * k + 1) : (4 * k + 0);
            const bool s1 = p1.y > p1.x;
            tv[2 * k + 1] = fmaxf(p1.x, p1.y);
            ti[2 * k + 1] = s1 ? (4 * k + 3) : (4 * k + 2);
        }
        // L2..L5 (left wins ties -> first occurrence)
        float uv[8]; int ui[8];
        #pragma unroll
        for (int i = 0; i < 8; ++i) {
            const bool p = tv[2 * i + 1] > tv[2 * i];
            uv[i] = fmaxf(tv[2 * i], tv[2 * i + 1]);
            ui[i] = p ? ti[2 * i + 1] : ti[2 * i];
        }
        float wv[4]; int wi[4];
        #pragma unroll
        for (int i = 0; i < 4; ++i) {
            const bool p = uv[2 * i + 1] > uv[2 * i];
            wv[i] = fmaxf(uv[2 * i], uv[2 * i + 1]);
            wi[i] = p ? ui[2 * i + 1] : ui[2 * i];
        }
        const bool pa = wv[1] > wv[0];
        const float xv0 = fmaxf(wv[0], wv[1]);
        const int   xi0 = pa ? wi[1] : wi[0];
        const bool pb = wv[3] > wv[2];
        const float xv1 = fmaxf(wv[2], wv[3]);
        const int   xi1 = pb ? wi[3] : wi[2];
        const bool pc = xv1 > xv0;
        const float m  = fmaxf(xv0, xv1);
        const int   bi = pc ? xi1 : xi0;

        const float nv = m + emt;
        if (AM) {
            v = nv;
            hb[(size_t)(t - 1) * Tn + j] = (unsigned char)bi;
        } else {
            const int m_ = mk[t];
            const int bp = m_ ? bi : j;
            v = m_ ? nv : v;
            hb[(size_t)(t - 1) * Tn + j] = (unsigned char)bp;
        }

        const int tf = t + RD;
        const int tcl = tf < Sn - 1 ? tf : Sn - 1;
        cp4(rbase + ((((tf & 15) * 32) + j) << 2), em + (size_t)tcl * Tn + j);
        CP_COMMIT();
    }
    // last_tag = argmax_j (v_j + end_j), lowest index on ties
    float bv = v + endv[j];
    int   bidx = j;
    #pragma unroll
    for (int off = 16; off; off >>= 1) {
        const float ov = __shfl_xor_sync(FULLMASK, bv, off);
        const int   oi = __shfl_xor_sync(FULLMASK, bidx, off);
        const bool take = (ov > bv) || (ov == bv && oi < bidx);
        bv   = take ? ov : bv;
        bidx = take ? oi : bidx;
    }
    if (j == 0) g_last[b] = bidx;
}

// ---------------------------------------------------------------------------
// Main kernel: 128 CTAs x 128 threads, wave-1 (1 CTA/SM), 1 long warp/SMSP:
//   wid 0: fwd  batch 2*bid      wid 1: fwd  batch 2*bid+1
//   wid 2: vit  batch 2*bid      wid 3: vit  batch 2*bid+1
// ---------------------------------------------------------------------------
__global__ __launch_bounds__(128)
void crf_main_kernel(const float* __restrict__ pred,
                     const int*   __restrict__ amask,
                     const float* __restrict__ startv,
                     const float* __restrict__ endv,
                     const float* __restrict__ trans)
{
    const int wib = threadIdx.x >> 5;
    const int j   = threadIdx.x & 31;
    const int wb  = wib & 1;                 // which of the 2 batches
    const int b   = (blockIdx.x << 1) | wb;

    __shared__ __align__(16) float ring[4][16][32];
    __shared__ __align__(16) float buf[4][2][32];
    __shared__ signed char mkS[2][Sn];
    __shared__ int s_allones[2];

    if (wib < 2) {
        // mask load + all-ones detect (one warp per batch)
        const int* am = amask + (size_t)b * Sn;
        int okv = 1;
        for (int t = j; t < Sn; t += 32) {
            const int mv = am[t];
            mkS[wb][t] = (signed char)mv;
            okv &= (mv == 1);
        }
        const bool ao = __all_sync(FULLMASK, okv != 0);
        if (j == 0) s_allones[wb] = ao ? 1 : 0;
    }
    __syncthreads();

    const float* em = pred + (size_t)b * Sn * Tn;
    float* bufw  = &buf[wib][0][0];
    float* ringw = &ring[wib][0][0];

    if (wib < 2) {
        if (s_allones[wb])
            fwd_loop<true >(em, j, bufw, ringw, mkS[wb], startv, endv, trans, b);
        else
            fwd_loop<false>(em, j, bufw, ringw, mkS[wb], startv, endv, trans, b);
    } else {
        if (s_allones[wb])
            vit_loop<true >(em, j, bufw, ringw, mkS[wb], startv, endv, trans, b);
        else
            vit_loop<false>(em, j, bufw, ringw, mkS[wb], startv, endv, trans, b);
    }
}

// ---------------------------------------------------------------------------
// Backtrace phase 1 (+ numerator blocks): blocks 0..1023 compute per-chunk
// tag maps; blocks 1024..1087 compute the numerator (4 batches each).
// ---------------------------------------------------------------------------
__global__ __launch_bounds__(128)
void bt_phase1(const float* __restrict__ pred,
               const int*   __restrict__ amask,
               const int*   __restrict__ labels,
               const float* __restrict__ startv,
               const float* __restrict__ endv,
               const float* __restrict__ trans)
{
    const int wib  = threadIdx.x >> 5;
    const int lane = threadIdx.x & 31;

    if (blockIdx.x >= (Bn * NCH) / 4) {
        // ------- Numerator: one warp per batch ------------------------------
        const int b = ((int)blockIdx.x - (Bn * NCH) / 4) * 4 + wib;
        const float* em = pred + (size_t)b * Sn * Tn;
        const int* lab = labels + (size_t)b * Sn;
        const int* am  = amask  + (size_t)b * Sn;
        float sum = 0.f;
        int   msum = 0;
        for (int t = lane; t < Sn; t += 32) {
            const int mt = am[t];
            msum += mt;
            const int tg = lab[t];
            if (t == 0) {
                sum += startv[tg] + em[tg];
            } else {
                const int tp = lab[t - 1];
                sum += (trans[tp * Tn + tg] + em[(size_t)t * Tn + tg]) * (float)mt;
            }
        }
        #pragma unroll
        for (int off = 16; off; off >>= 1) {
            sum  += __shfl_xor_sync(FULLMASK, sum, off);
            msum += __shfl_xor_sync(FULLMASK, msum, off);
        }
        if (lane == 0) {
            const int se = msum - 1;
            const int lt = lab[se];
            g_num[b] = sum + endv[lt];
        }
        return;
    }

    const int gw = (blockIdx.x << 2) | wib;       // 0 .. Bn*NCH-1
    const int b = gw >> 6;
    const int c = gw & 63;
    const int lo = c * 32;
    int hi = lo + 31; if (hi > Sn - 2) hi = Sn - 2;
    const int n = hi - lo + 1;

    __shared__ __align__(16) unsigned char sm[4][32 * Tn];
    unsigned char* S = sm[wib];
    const uint32_t* src = (const uint32_t*)(g_hist + ((size_t)b * (Sn - 1) + lo) * Tn);
    uint32_t* dst = (uint32_t*)S;
    for (int i = lane; i < n * 8; i += 32) dst[i] = src[i];
    __syncwarp();

    int tag = lane;
    for (int k = n - 1; k >= 0; --k) tag = S[k * Tn + tag];
    g_map[b][c][lane] = (unsigned char)tag;
}

// ---------------------------------------------------------------------------
// Backtrace phase 2: per batch, compose the 64 chunk maps from the top.
// ---------------------------------------------------------------------------
__global__ __launch_bounds__(128)
void bt_phase2(float* __restrict__ out)
{
    const int wib  = threadIdx.x >> 5;
    const int lane = threadIdx.x & 31;
    const int b = (blockIdx.x << 2) | wib;

    __shared__ __align__(16) unsigned char sm[4][NCH * Tn];
    __shared__ unsigned char se[4][NCH];
    unsigned char* S = sm[wib];
    const uint32_t* src = (const uint32_t*)&g_map[b][0][0];
    uint32_t* dst = (uint32_t*)S;
    for (int i = lane; i < NCH * Tn / 4; i += 32) dst[i] = src[i];
    __syncwarp();

    if (lane == 0) {
        int e = g_last[b];
        out[(size_t)b * Sn + (Sn - 1)] = (float)e;
        for (int c = NCH - 1; c >= 0; --c) {
            se[wib][c] = (unsigned char)e;   // entry tag for chunk c
            e = S[c * Tn + e];               // exit = map[entry]
        }
    }
    __syncwarp();
    for (int c = lane; c < NCH; c += 32) g_ent[b][c] = se[wib][c];
}

// ---------------------------------------------------------------------------
// Backtrace phase 3: re-chase each chunk from its entry tag; coalesced write.
// ---------------------------------------------------------------------------
__global__ __launch_bounds__(128)
void bt_phase3(float* __restrict__ out)
{
    const int wib  = threadIdx.x >> 5;
    const int lane = threadIdx.x & 31;
    const int gw = (blockIdx.x << 2) | wib;
    const int b = gw >> 6;
    const int c = gw & 63;
    const int lo = c * 32;
    int hi = lo + 31; if (hi > Sn - 2) hi = Sn - 2;
    const int n = hi - lo + 1;

    __shared__ __align__(16) unsigned char sm[4][32 * Tn];
    __shared__ unsigned char stag[4][32];
    unsigned char* S = sm[wib];
    const uint32_t* src = (const uint32_t*)(g_hist + ((size_t)b * (Sn - 1) + lo) * Tn);
    uint32_t* dst = (uint32_t*)S;
    for (int i = lane; i < n * 8; i += 32) dst[i] = src[i];
    __syncwarp();

    if (lane == 0) {
        int tag = g_ent[b][c];
        for (int k = n - 1; k >= 0; --k) {
            tag = S[k * Tn + tag];
            stag[wib][k] = (unsigned char)tag;
        }
    }
    __syncwarp();
    if (lane < n) out[(size_t)b * Sn + lo + lane] = (float)stag[wib][lane];
}

// ---------------------------------------------------------------------------
// Loss: -mean(num - den)
// ---------------------------------------------------------------------------
__global__ void crf_loss_kernel(float* __restrict__ out)
{
    __shared__ float red[Bn];
    const int t = threadIdx.x;
    red[t] = g_num[t] - g_den[t];
    __syncthreads();
    #pragma unroll
    for (int off = 128; off; off >>= 1) {
        if (t < off) red[t] += red[t + off];
        __syncthreads();
    }
    if (t == 0) out[(size_t)Bn * Sn] = -(red[0] / (float)Bn);
}

extern "C" void kernel_launch(void* const* d_in, const int* in_sizes, int n_in,
                              void* d_out, int out_size)
{
    const float* pred   = (const float*)d_in[0];
    const int*   amask  = (const int*)  d_in[1];
    const int*   labels = (const int*)  d_in[2];
    const float* startv = (const float*)d_in[3];
    const float* endv   = (const float*)d_in[4];
    const float* trans  = (const float*)d_in[5];
    float* out = (float*)d_out;

    crf_main_kernel<<<128, 128>>>(pred, amask, startv, endv, trans);
    bt_phase1<<<(Bn * NCH) / 4 + Bn / 4, 128>>>(pred, amask, labels, startv, endv, trans);
    bt_phase2<<<Bn / 4, 128>>>(out);
    bt_phase3<<<(Bn * NCH) / 4, 128>>>(out);
    crf_loss_kernel<<<1, Bn>>>(out);
}

// round 13
// speedup vs baseline: 1.3242x; 1.0599x over previous
#include <cuda_runtime.h>
#include <cuda_bf16.h>
#include <cstdint>

#define Bn 256
#define Sn 2048
#define Tn 32
#define NCH 64
#define NG  (Sn / 4)          // 512 groups of 4 timesteps
#define FULLMASK 0xffffffffu
#define LOG32F 3.4657359027997265f

// Scratch (device globals are the sanctioned scratch mechanism)
__device__ unsigned char g_hist[(size_t)Bn * (Sn - 1) * Tn];  // backpointers
__device__ unsigned char g_map[Bn][NCH][Tn];                  // chunk tag maps
__device__ unsigned char g_ent[Bn][NCH];                      // chunk entry tags
__device__ float g_den[Bn];
__device__ float g_num[Bn];
__device__ int   g_last[Bn];

// ---- packed f32x2 helpers (Blackwell) -------------------------------------
__device__ __forceinline__ float2 fadd2(float2 a, float2 b) {
    union { float2 f; unsigned long long u; } A, B, R;
    A.f = a; B.f = b;
    asm("add.rn.f32x2 %0, %1, %2;" : "=l"(R.u) : "l"(A.u), "l"(B.u));
    return R.f;
}
__device__ __forceinline__ float2 ffma2(float2 a, float2 b, float2 c) {
    union { float2 f; unsigned long long u; } A, B, C, R;
    A.f = a; B.f = b; C.f = c;
    asm("fma.rn.f32x2 %0, %1, %2, %3;" : "=l"(R.u) : "l"(A.u), "l"(B.u), "l"(C.u));
    return R.f;
}

// ---- cp.async helpers ------------------------------------------------------
__device__ __forceinline__ uint32_t smem_u32(const void* p) {
    return (uint32_t)__cvta_generic_to_shared(p);
}
__device__ __forceinline__ void cp16(uint32_t d, const void* s) {
    asm volatile("cp.async.cg.shared.global [%0], [%1], 16;" :: "r"(d), "l"(s));
}
#define CP_COMMIT() asm volatile("cp.async.commit_group;")
#define CP_WAIT2()  asm volatile("cp.async.wait_group 2;")

// Ring: 4 groups x (4 rows x 32 floats) = 512 floats per warp.
// Group g holds em rows 4g..4g+3 linearly. One cp16/lane fetches a group.

// ---------------------------------------------------------------------------
// Forward algorithm, linear domain with deferred renorm. em via grouped ring.
// ---------------------------------------------------------------------------
template<bool AM>
__device__ __forceinline__ void fwd_loop(const float* __restrict__ em, int j,
                                         float* __restrict__ bufw,
                                         float* __restrict__ ringw,
                                         const signed char* __restrict__ mk,
                                         const float* __restrict__ startv,
                                         const float* __restrict__ endv,
                                         const float* __restrict__ trans,
                                         int b)
{
    float2 tc2[16];
    #pragma unroll
    for (int k = 0; k < 16; ++k) {
        float2 p;
        p.x = __expf(trans[(2 * k + 0) * Tn + j]) * 0.03125f;
        p.y = __expf(trans[(2 * k + 1) * Tn + j]) * 0.03125f;
        tc2[k] = p;
    }

    const uint32_t rbase = smem_u32(ringw);
    #pragma unroll
    for (int g = 0; g < 3; ++g) {
        cp16(rbase + (uint32_t)(g * 512 + j * 16), em + (size_t)g * 128 + j * 4);
        CP_COMMIT();
    }

    float s  = __expf(startv[j] + em[j]);
    float Lr = 0.f;
    int   nm = 0;

    auto step = [&](int t, float emv, bool renorm) {
        float* sb = bufw + (t & 1) * 32;
        sb[j] = s;
        __syncwarp();
        const float ee = __expf(emv);

        float2 a0 = {0.f, 0.f}, a1 = {0.f, 0.f}, a2 = {0.f, 0.f}, a3 = {0.f, 0.f};
        #pragma unroll
        for (int k = 0; k < 4; ++k) {
            const float4 qa = *(const float4*)(sb + 8 * k);
            const float4 qb = *(const float4*)(sb + 8 * k + 4);
            a0 = ffma2(make_float2(qa.x, qa.y), tc2[4 * k + 0], a0);
            a1 = ffma2(make_float2(qa.z, qa.w), tc2[4 * k + 1], a1);
            a2 = ffma2(make_float2(qb.x, qb.y), tc2[4 * k + 2], a2);
            a3 = ffma2(make_float2(qb.z, qb.w), tc2[4 * k + 3], a3);
        }
        const float2 a01 = fadd2(a0, a1);
        const float2 a23 = fadd2(a2, a3);
        const float2 aa  = fadd2(a01, a23);
        const float ns = (aa.x + aa.y) * ee;
        if (AM) {
            s = ns;
        } else {
            const int m_ = mk[t];
            s = m_ ? ns : s;
            nm += (m_ != 0);
        }
        if (renorm) {                                  // t % 16 == 15
            const float r  = __shfl_sync(FULLMASK, s, 0);
            const float rr = __frcp_rn(r);
            s *= rr;
            Lr -= __logf(rr);
        }
    };

    // group 0 (t = 1..3)
    {
        CP_WAIT2();
        const float* grp = ringw;
        #pragma unroll
        for (int u = 1; u < 4; ++u) step(u, grp[u * 32 + j], false);
        cp16(rbase + (uint32_t)(3 & 3) * 512 + j * 16, em + (size_t)3 * 128 + j * 4);
        CP_COMMIT();
    }
    #pragma unroll 1
    for (int g = 1; g < NG; ++g) {
        CP_WAIT2();
        const float* grp = ringw + (g & 3) * 128;
        #pragma unroll
        for (int u = 0; u < 4; ++u)
            step(4 * g + u, grp[u * 32 + j], (u == 3) && ((g & 3) == 3));
        const int gn = (g + 3 < NG) ? (g + 3) : (NG - 1);
        cp16(rbase + (uint32_t)((g + 3) & 3) * 512 + j * 16,
             em + (size_t)gn * 128 + j * 4);
        CP_COMMIT();
    }

    if (AM) nm = Sn - 1;
    float v = s * __expf(endv[j]);
    #pragma unroll
    for (int off = 16; off; off >>= 1)
        v += __shfl_xor_sync(FULLMASK, v, off);
    if (j == 0) g_den[b] = (float)nm * LOG32F + Lr + __logf(v);
}

// ---------------------------------------------------------------------------
// Viterbi with tournament argmax (r12-verified). em via grouped ring.
// ---------------------------------------------------------------------------
template<bool AM>
__device__ __forceinline__ void vit_loop(const float* __restrict__ em, int j,
                                         float* __restrict__ bufw,
                                         float* __restrict__ ringw,
                                         const signed char* __restrict__ mk,
                                         const float* __restrict__ startv,
                                         const float* __restrict__ endv,
                                         const float* __restrict__ trans,
                                         int b)
{
    float2 tc2[16];
    #pragma unroll
    for (int k = 0; k < 16; ++k) {
        float2 p;
        p.x = trans[(2 * k + 0) * Tn + j];
        p.y = trans[(2 * k + 1) * Tn + j];
        tc2[k] = p;
    }

    const uint32_t rbase = smem_u32(ringw);
    #pragma unroll
    for (int g = 0; g < 3; ++g) {
        cp16(rbase + (uint32_t)(g * 512 + j * 16), em + (size_t)g * 128 + j * 4);
        CP_COMMIT();
    }

    float v = startv[j] + em[j];
    unsigned char* hb = g_hist + (size_t)b * (Sn - 1) * Tn;

    auto step = [&](int t, float emt) {
        float* vb = bufw + (t & 1) * 32;
        vb[j] = v;
        __syncwarp();

        // L1: 16 merged pairs (value + index), left-priority strict '>'
        float tv[16]; int ti[16];
        #pragma unroll
        for (int k = 0; k < 8; ++k) {
            const float4 q = *(const float4*)(vb + 4 * k);
            const float2 p0 = fadd2(make_float2(q.x, q.y), tc2[2 * k + 0]);
            const float2 p1 = fadd2(make_float2(q.z, q.w), tc2[2 * k + 1]);
            const bool s0 = p0.y > p0.x;
            tv[2 * k + 0] = fmaxf(p0.x, p0.y);
            ti[2 * k + 0] = s0 ? (4 * k + 1) : (4 * k + 0);
            const bool s1 = p1.y > p1.x;
            tv[2 * k + 1] = fmaxf(p1.x, p1.y);
            ti[2 * k + 1] = s1 ? (4 * k + 3) : (4 * k + 2);
        }
        float uv[8]; int ui[8];
        #pragma unroll
        for (int i = 0; i < 8; ++i) {
            const bool p = tv[2 * i + 1] > tv[2 * i];
            uv[i] = fmaxf(tv[2 * i], tv[2 * i + 1]);
            ui[i] = p ? ti[2 * i + 1] : ti[2 * i];
        }
        float wv[4]; int wi[4];
        #pragma unroll
        for (int i = 0; i < 4; ++i) {
            const bool p = uv[2 * i + 1] > uv[2 * i];
            wv[i] = fmaxf(uv[2 * i], uv[2 * i + 1]);
            wi[i] = p ? ui[2 * i + 1] : ui[2 * i];
        }
        const bool pa = wv[1] > wv[0];
        const float xv0 = fmaxf(wv[0], wv[1]);
        const int   xi0 = pa ? wi[1] : wi[0];
        const bool pb = wv[3] > wv[2];
        const float xv1 = fmaxf(wv[2], wv[3]);
        const int   xi1 = pb ? wi[3] : wi[2];
        const bool pc = xv1 > xv0;
        const float m  = fmaxf(xv0, xv1);
        const int   bi = pc ? xi1 : xi0;

        const float nv = m + emt;
        if (AM) {
            v = nv;
            hb[(size_t)(t - 1) * Tn + j] = (unsigned char)bi;
        } else {
            const int m_ = mk[t];
            const int bp = m_ ? bi : j;
            v = m_ ? nv : v;
            hb[(size_t)(t - 1) * Tn + j] = (unsigned char)bp;
        }
    };

    // group 0 (t = 1..3)
    {
        CP_WAIT2();
        const float* grp = ringw;
        #pragma unroll
        for (int u = 1; u < 4; ++u) step(u, grp[u * 32 + j]);
        cp16(rbase + (uint32_t)(3 & 3) * 512 + j * 16, em + (size_t)3 * 128 + j * 4);
        CP_COMMIT();
    }
    #pragma unroll 1
    for (int g = 1; g < NG; ++g) {
        CP_WAIT2();
        const float* grp = ringw + (g & 3) * 128;
        #pragma unroll
        for (int u = 0; u < 4; ++u) step(4 * g + u, grp[u * 32 + j]);
        const int gn = (g + 3 < NG) ? (g + 3) : (NG - 1);
        cp16(rbase + (uint32_t)((g + 3) & 3) * 512 + j * 16,
             em + (size_t)gn * 128 + j * 4);
        CP_COMMIT();
    }

    // last_tag = argmax_j (v_j + end_j), lowest index on ties
    float bv = v + endv[j];
    int   bidx = j;
    #pragma unroll
    for (int off = 16; off; off >>= 1) {
        const float ov = __shfl_xor_sync(FULLMASK, bv, off);
        const int   oi = __shfl_xor_sync(FULLMASK, bidx, off);
        const bool take = (ov > bv) || (ov == bv && oi < bidx);
        bv   = take ? ov : bv;
        bidx = take ? oi : bidx;
    }
    if (j == 0) g_last[b] = bidx;
}

// ---------------------------------------------------------------------------
// Main kernel: 128 CTAs x 128 threads, wave-1 (1 CTA/SM), 1 long warp/SMSP:
//   wid 0: fwd  batch 2*bid      wid 1: fwd  batch 2*bid+1
//   wid 2: vit  batch 2*bid      wid 3: vit  batch 2*bid+1
// ---------------------------------------------------------------------------
__global__ __launch_bounds__(128)
void crf_main_kernel(const float* __restrict__ pred,
                     const int*   __restrict__ amask,
                     const float* __restrict__ startv,
                     const float* __restrict__ endv,
                     const float* __restrict__ trans)
{
    const int wib = threadIdx.x >> 5;
    const int j   = threadIdx.x & 31;
    const int wb  = wib & 1;                 // which of the 2 batches
    const int b   = (blockIdx.x << 1) | wb;

    __shared__ __align__(16) float ring[4][512];
    __shared__ __align__(16) float buf[4][2][32];
    __shared__ signed char mkS[2][Sn];
    __shared__ int s_allones[2];

    if (wib < 2) {
        // mask load + all-ones detect (one warp per batch)
        const int* am = amask + (size_t)b * Sn;
        int okv = 1;
        for (int t = j; t < Sn; t += 32) {
            const int mv = am[t];
            mkS[wb][t] = (signed char)mv;
            okv &= (mv == 1);
        }
        const bool ao = __all_sync(FULLMASK, okv != 0);
        if (j == 0) s_allones[wb] = ao ? 1 : 0;
    }
    __syncthreads();

    const float* em = pred + (size_t)b * Sn * Tn;
    float* bufw  = &buf[wib][0][0];
    float* ringw = &ring[wib][0];

    if (wib < 2) {
        if (s_allones[wb])
            fwd_loop<true >(em, j, bufw, ringw, mkS[wb], startv, endv, trans, b);
        else
            fwd_loop<false>(em, j, bufw, ringw, mkS[wb], startv, endv, trans, b);
    } else {
        if (s_allones[wb])
            vit_loop<true >(em, j, bufw, ringw, mkS[wb], startv, endv, trans, b);
        else
            vit_loop<false>(em, j, bufw, ringw, mkS[wb], startv, endv, trans, b);
    }
}

// ---------------------------------------------------------------------------
// Backtrace phase 1 (+ numerator blocks): blocks 0..1023 compute per-chunk
// tag maps; blocks 1024..1087 compute the numerator (4 batches each).
// ---------------------------------------------------------------------------
__global__ __launch_bounds__(128)
void bt_phase1(const float* __restrict__ pred,
               const int*   __restrict__ amask,
               const int*   __restrict__ labels,
               const float* __restrict__ startv,
               const float* __restrict__ endv,
               const float* __restrict__ trans)
{
    const int wib  = threadIdx.x >> 5;
    const int lane = threadIdx.x & 31;

    if (blockIdx.x >= (Bn * NCH) / 4) {
        // ------- Numerator: one warp per batch ------------------------------
        const int b = ((int)blockIdx.x - (Bn * NCH) / 4) * 4 + wib;
        const float* em = pred + (size_t)b * Sn * Tn;
        const int* lab = labels + (size_t)b * Sn;
        const int* am  = amask  + (size_t)b * Sn;
        float sum = 0.f;
        int   msum = 0;
        for (int t = lane; t < Sn; t += 32) {
            const int mt = am[t];
            msum += mt;
            const int tg = lab[t];
            if (t == 0) {
                sum += startv[tg] + em[tg];
            } else {
                const int tp = lab[t - 1];
                sum += (trans[tp * Tn + tg] + em[(size_t)t * Tn + tg]) * (float)mt;
            }
        }
        #pragma unroll
        for (int off = 16; off; off >>= 1) {
            sum  += __shfl_xor_sync(FULLMASK, sum, off);
            msum += __shfl_xor_sync(FULLMASK, msum, off);
        }
        if (lane == 0) {
            const int se = msum - 1;
            const int lt = lab[se];
            g_num[b] = sum + endv[lt];
        }
        return;
    }

    const int gw = (blockIdx.x << 2) | wib;       // 0 .. Bn*NCH-1
    const int b = gw >> 6;
    const int c = gw & 63;
    const int lo = c * 32;
    int hi = lo + 31; if (hi > Sn - 2) hi = Sn - 2;
    const int n = hi - lo + 1;

    __shared__ __align__(16) unsigned char sm[4][32 * Tn];
    unsigned char* S = sm[wib];
    const uint32_t* src = (const uint32_t*)(g_hist + ((size_t)b * (Sn - 1) + lo) * Tn);
    uint32_t* dst = (uint32_t*)S;
    for (int i = lane; i < n * 8; i += 32) dst[i] = src[i];
    __syncwarp();

    int tag = lane;
    for (int k = n - 1; k >= 0; --k) tag = S[k * Tn + tag];
    g_map[b][c][lane] = (unsigned char)tag;
}

// ---------------------------------------------------------------------------
// Backtrace phase 2: per batch, compose the 64 chunk maps from the top.
// Block 64 computes the loss (g_num/g_den are complete after bt_phase1).
// ---------------------------------------------------------------------------
__global__ __launch_bounds__(128)
void bt_phase2(float* __restrict__ out)
{
    if (blockIdx.x == Bn / 4) {
        // ------- Loss: -mean(num - den) -------------------------------------
        __shared__ float red[128];
        const int t = threadIdx.x;
        red[t] = (g_num[t] - g_den[t]) + (g_num[t + 128] - g_den[t + 128]);
        __syncthreads();
        #pragma unroll
        for (int off = 64; off; off >>= 1) {
            if (t < off) red[t] += red[t + off];
            __syncthreads();
        }
        if (t == 0) out[(size_t)Bn * Sn] = -(red[0] / (float)Bn);
        return;
    }

    const int wib  = threadIdx.x >> 5;
    const int lane = threadIdx.x & 31;
    const int b = (blockIdx.x << 2) | wib;

    __shared__ __align__(16) unsigned char sm[4][NCH * Tn];
    __shared__ unsigned char se[4][NCH];
    unsigned char* S = sm[wib];
    const uint32_t* src = (const uint32_t*)&g_map[b][0][0];
    uint32_t* dst = (uint32_t*)S;
    for (int i = lane; i < NCH * Tn / 4; i += 32) dst[i] = src[i];
    __syncwarp();

    if (lane == 0) {
        int e = g_last[b];
        out[(size_t)b * Sn + (Sn - 1)] = (float)e;
        for (int c = NCH - 1; c >= 0; --c) {
            se[wib][c] = (unsigned char)e;   // entry tag for chunk c
            e = S[c * Tn + e];               // exit = map[entry]
        }
    }
    __syncwarp();
    for (int c = lane; c < NCH; c += 32) g_ent[b][c] = se[wib][c];
}

// ---------------------------------------------------------------------------
// Backtrace phase 3: re-chase each chunk from its entry tag; coalesced write.
// ---------------------------------------------------------------------------
__global__ __launch_bounds__(128)
void bt_phase3(float* __restrict__ out)
{
    const int wib  = threadIdx.x >> 5;
    const int lane = threadIdx.x & 31;
    const int gw = (blockIdx.x << 2) | wib;
    const int b = gw >> 6;
    const int c = gw & 63;
    const int lo = c * 32;
    int hi = lo + 31; if (hi > Sn - 2) hi = Sn - 2;
    const int n = hi - lo + 1;

    __shared__ __align__(16) unsigned char sm[4][32 * Tn];
    __shared__ unsigned char stag[4][32];
    unsigned char* S = sm[wib];
    const uint32_t* src = (const uint32_t*)(g_hist + ((size_t)b * (Sn - 1) + lo) * Tn);
    uint32_t* dst = (uint32_t*)S;
    for (int i = lane; i < n * 8; i += 32) dst[i] = src[i];
    __syncwarp();

    if (lane == 0) {
        int tag = g_ent[b][c];
        for (int k = n - 1; k >= 0; --k) {
            tag = S[k * Tn + tag];
            stag[wib][k] = (unsigned char)tag;
        }
    }
    __syncwarp();
    if (lane < n) out[(size_t)b * Sn + lo + lane] = (float)stag[wib][lane];
}

extern "C" void kernel_launch(void* const* d_in, const int* in_sizes, int n_in,
                              void* d_out, int out_size)
{
    const float* pred   = (const float*)d_in[0];
    const int*   amask  = (const int*)  d_in[1];
    const int*   labels = (const int*)  d_in[2];
    const float* startv = (const float*)d_in[3];
    const float* endv   = (const float*)d_in[4];
    const float* trans  = (const float*)d_in[5];
    float* out = (float*)d_out;

    crf_main_kernel<<<128, 128>>>(pred, amask, startv, endv, trans);
    bt_phase1<<<(Bn * NCH) / 4 + Bn / 4, 128>>>(pred, amask, labels, startv, endv, trans);
    bt_phase2<<<Bn / 4 + 1, 128>>>(out);
    bt_phase3<<<(Bn * NCH) / 4, 128>>>(out);
}

// round 15
// speedup vs baseline: 1.3296x; 1.0041x over previous
#include <cuda_runtime.h>
#include <cuda_bf16.h>
#include <cstdint>

#define Bn 256
#define Sn 2048
#define Tn 32
#define NCH 64
#define NG  (Sn / 4)          // 512 groups of 4 timesteps
#define FULLMASK 0xffffffffu
#define LOG32F 3.4657359027997265f

// Scratch (device globals are the sanctioned scratch mechanism)
__device__ unsigned char g_hist[(size_t)Bn * (Sn - 1) * Tn];  // backpointers
__device__ unsigned char g_map[Bn][NCH][Tn];                  // chunk tag maps
__device__ unsigned char g_ent[Bn][NCH];                      // chunk entry tags
__device__ float g_den[Bn];
__device__ float g_num[Bn];
__device__ int   g_last[Bn];

// ---- packed f32x2 helpers (Blackwell) -------------------------------------
__device__ __forceinline__ float2 fadd2(float2 a, float2 b) {
    union { float2 f; unsigned long long u; } A, B, R;
    A.f = a; B.f = b;
    asm("add.rn.f32x2 %0, %1, %2;" : "=l"(R.u) : "l"(A.u), "l"(B.u));
    return R.f;
}
__device__ __forceinline__ float2 ffma2(float2 a, float2 b, float2 c) {
    union { float2 f; unsigned long long u; } A, B, C, R;
    A.f = a; B.f = b; C.f = c;
    asm("fma.rn.f32x2 %0, %1, %2, %3;" : "=l"(R.u) : "l"(A.u), "l"(B.u), "l"(C.u));
    return R.f;
}

// ---- cp.async helpers ------------------------------------------------------
__device__ __forceinline__ uint32_t smem_u32(const void* p) {
    return (uint32_t)__cvta_generic_to_shared(p);
}
__device__ __forceinline__ void cp16(uint32_t d, const void* s) {
    asm volatile("cp.async.cg.shared.global [%0], [%1], 16;" :: "r"(d), "l"(s));
}
#define CP_COMMIT() asm volatile("cp.async.commit_group;")
#define CP_WAIT2()  asm volatile("cp.async.wait_group 2;")

// Ring: 4 groups x (4 rows x 32 floats) = 512 floats per warp.
// Group g holds em rows 4g..4g+3 linearly. One cp16/lane fetches a group.

// ---------------------------------------------------------------------------
// Forward algorithm, linear domain with deferred renorm. em via grouped ring;
// all 4 em loads + exps hoisted to group start (off the per-step chain).
// ---------------------------------------------------------------------------
template<bool AM>
__device__ __forceinline__ void fwd_loop(const float* __restrict__ em, int j,
                                         float* __restrict__ bufw,
                                         float* __restrict__ ringw,
                                         const signed char* __restrict__ mk,
                                         const float* __restrict__ startv,
                                         const float* __restrict__ endv,
                                         const float* __restrict__ trans,
                                         int b)
{
    float2 tc2[16];
    #pragma unroll
    for (int k = 0; k < 16; ++k) {
        float2 p;
        p.x = __expf(trans[(2 * k + 0) * Tn + j]) * 0.03125f;
        p.y = __expf(trans[(2 * k + 1) * Tn + j]) * 0.03125f;
        tc2[k] = p;
    }

    const uint32_t rbase = smem_u32(ringw);
    #pragma unroll
    for (int g = 0; g < 3; ++g) {
        cp16(rbase + (uint32_t)(g * 512 + j * 16), em + (size_t)g * 128 + j * 4);
        CP_COMMIT();
    }

    float s  = __expf(startv[j] + em[j]);
    float Lr = 0.f;
    int   nm = 0;

    bufw[j] = s;                     // slot 0 holds state at t=0
    __syncwarp();

    auto step = [&](int t, float ee, bool renorm) {
        const float* sb = bufw + ((t + 1) & 1) * 32;   // state t-1

        float2 a0 = {0.f, 0.f}, a1 = {0.f, 0.f}, a2 = {0.f, 0.f}, a3 = {0.f, 0.f};
        #pragma unroll
        for (int k = 0; k < 4; ++k) {
            const float4 qa = *(const float4*)(sb + 8 * k);
            const float4 qb = *(const float4*)(sb + 8 * k + 4);
            a0 = ffma2(make_float2(qa.x, qa.y), tc2[4 * k + 0], a0);
            a1 = ffma2(make_float2(qa.z, qa.w), tc2[4 * k + 1], a1);
            a2 = ffma2(make_float2(qb.x, qb.y), tc2[4 * k + 2], a2);
            a3 = ffma2(make_float2(qb.z, qb.w), tc2[4 * k + 3], a3);
        }
        const float2 a01 = fadd2(a0, a1);
        const float2 a23 = fadd2(a2, a3);
        const float2 aa  = fadd2(a01, a23);
        const float ns = (aa.x + aa.y) * ee;
        if (AM) {
            s = ns;
        } else {
            const int m_ = mk[t];
            s = m_ ? ns : s;
            nm += (m_ != 0);
        }
        if (renorm) {                                  // t % 16 == 15 (pre-store!)
            const float r  = __shfl_sync(FULLMASK, s, 0);
            const float rr = __frcp_rn(r);
            s *= rr;
            Lr -= __logf(rr);
        }
        bufw[(t & 1) * 32 + j] = s;
        __syncwarp();
    };

    // group 0 (t = 1..3)
    {
        CP_WAIT2();
        const float* grp = ringw;
        float ee1 = __expf(grp[1 * 32 + j]);
        float ee2 = __expf(grp[2 * 32 + j]);
        float ee3 = __expf(grp[3 * 32 + j]);
        step(1, ee1, false);
        step(2, ee2, false);
        step(3, ee3, false);
        cp16(rbase + (uint32_t)(3 & 3) * 512 + j * 16, em + (size_t)3 * 128 + j * 4);
        CP_COMMIT();
    }
    #pragma unroll 1
    for (int g = 1; g < NG; ++g) {
        CP_WAIT2();
        const float* grp = ringw + (g & 3) * 128;
        float ee0 = __expf(grp[0 * 32 + j]);
        float ee1 = __expf(grp[1 * 32 + j]);
        float ee2 = __expf(grp[2 * 32 + j]);
        float ee3 = __expf(grp[3 * 32 + j]);
        const bool rn = ((g & 3) == 3);
        step(4 * g + 0, ee0, false);
        step(4 * g + 1, ee1, false);
        step(4 * g + 2, ee2, false);
        step(4 * g + 3, ee3, rn);
        const int gn = (g + 3 < NG) ? (g + 3) : (NG - 1);
        cp16(rbase + (uint32_t)((g + 3) & 3) * 512 + j * 16,
             em + (size_t)gn * 128 + j * 4);
        CP_COMMIT();
    }

    if (AM) nm = Sn - 1;
    float v = s * __expf(endv[j]);
    #pragma unroll
    for (int off = 16; off; off >>= 1)
        v += __shfl_xor_sync(FULLMASK, v, off);
    if (j == 0) g_den[b] = (float)nm * LOG32F + Lr + __logf(v);
}

// ---------------------------------------------------------------------------
// Viterbi, tournament argmax SPLIT across the sync: value path (pairs + L1
// indices + FMNMX tree + em + select) commits state via STS+syncwarp early;
// the L2-L5 index resolution + hist store run post-sync, inside the next
// step's LDS shadow. Arithmetic/tie semantics identical to r12/r13 (verified).
// ---------------------------------------------------------------------------
template<bool AM>
__device__ __forceinline__ void vit_loop(const float* __restrict__ em, int j,
                                         float* __restrict__ bufw,
                                         float* __restrict__ ringw,
                                         const signed char* __restrict__ mk,
                                         const float* __restrict__ startv,
                                         const float* __restrict__ endv,
                                         const float* __restrict__ trans,
                                         int b)
{
    float2 tc2[16];
    #pragma unroll
    for (int k = 0; k < 16; ++k) {
        float2 p;
        p.x = trans[(2 * k + 0) * Tn + j];
        p.y = trans[(2 * k + 1) * Tn + j];
        tc2[k] = p;
    }

    const uint32_t rbase = smem_u32(ringw);
    #pragma unroll
    for (int g = 0; g < 3; ++g) {
        cp16(rbase + (uint32_t)(g * 512 + j * 16), em + (size_t)g * 128 + j * 4);
        CP_COMMIT();
    }

    float v = startv[j] + em[j];
    unsigned char* hb = g_hist + (size_t)b * (Sn - 1) * Tn;

    bufw[j] = v;                     // slot 0 holds state at t=0
    __syncwarp();

    auto step = [&](int t, float emt) {
        const float* vb = bufw + ((t + 1) & 1) * 32;   // state t-1

        // ---- value phase + L1 indices -------------------------------------
        float tv[16]; int ti[16];
        #pragma unroll
        for (int k = 0; k < 8; ++k) {
            const float4 q = *(const float4*)(vb + 4 * k);
            const float2 p0 = fadd2(make_float2(q.x, q.y), tc2[2 * k + 0]);
            const float2 p1 = fadd2(make_float2(q.z, q.w), tc2[2 * k + 1]);
            const bool s0 = p0.y > p0.x;
            tv[2 * k + 0] = fmaxf(p0.x, p0.y);
            ti[2 * k + 0] = s0 ? (4 * k + 1) : (4 * k + 0);
            const bool s1 = p1.y > p1.x;
            tv[2 * k + 1] = fmaxf(p1.x, p1.y);
            ti[2 * k + 1] = s1 ? (4 * k + 3) : (4 * k + 2);
        }
        float uv[8];
        #pragma unroll
        for (int i = 0; i < 8; ++i) uv[i] = fmaxf(tv[2 * i], tv[2 * i + 1]);
        float wv[4];
        #pragma unroll
        for (int i = 0; i < 4; ++i) wv[i] = fmaxf(uv[2 * i], uv[2 * i + 1]);
        const float xv0 = fmaxf(wv[0], wv[1]);
        const float xv1 = fmaxf(wv[2], wv[3]);
        const float m   = fmaxf(xv0, xv1);

        const float nv = m + emt;
        int m_ = 1;
        if (!AM) m_ = mk[t];
        v = m_ ? nv : v;
        bufw[(t & 1) * 32 + j] = v;          // commit state EARLY
        __syncwarp();

        // ---- index phase (post-sync, fills next step's LDS shadow) --------
        int ui[8];
        #pragma unroll
        for (int i = 0; i < 8; ++i)
            ui[i] = (tv[2 * i + 1] > tv[2 * i]) ? ti[2 * i + 1] : ti[2 * i];
        int wi[4];
        #pragma unroll
        for (int i = 0; i < 4; ++i)
            wi[i] = (uv[2 * i + 1] > uv[2 * i]) ? ui[2 * i + 1] : ui[2 * i];
        const int xi0 = (wv[1] > wv[0]) ? wi[1] : wi[0];
        const int xi1 = (wv[3] > wv[2]) ? wi[3] : wi[2];
        const int bi  = (xv1 > xv0) ? xi1 : xi0;
        const int bp  = m_ ? bi : j;
        hb[(size_t)(t - 1) * Tn + j] = (unsigned char)bp;
    };

    // group 0 (t = 1..3)
    {
        CP_WAIT2();
        const float* grp = ringw;
        const float e1 = grp[1 * 32 + j];
        const float e2 = grp[2 * 32 + j];
        const float e3 = grp[3 * 32 + j];
        step(1, e1);
        step(2, e2);
        step(3, e3);
        cp16(rbase + (uint32_t)(3 & 3) * 512 + j * 16, em + (size_t)3 * 128 + j * 4);
        CP_COMMIT();
    }
    #pragma unroll 1
    for (int g = 1; g < NG; ++g) {
        CP_WAIT2();
        const float* grp = ringw + (g & 3) * 128;
        const float e0 = grp[0 * 32 + j];
        const float e1 = grp[1 * 32 + j];
        const float e2 = grp[2 * 32 + j];
        const float e3 = grp[3 * 32 + j];
        step(4 * g + 0, e0);
        step(4 * g + 1, e1);
        step(4 * g + 2, e2);
        step(4 * g + 3, e3);
        const int gn = (g + 3 < NG) ? (g + 3) : (NG - 1);
        cp16(rbase + (uint32_t)((g + 3) & 3) * 512 + j * 16,
             em + (size_t)gn * 128 + j * 4);
        CP_COMMIT();
    }

    // last_tag = argmax_j (v_j + end_j), lowest index on ties
    float bv = v + endv[j];
    int   bidx = j;
    #pragma unroll
    for (int off = 16; off; off >>= 1) {
        const float ov = __shfl_xor_sync(FULLMASK, bv, off);
        const int   oi = __shfl_xor_sync(FULLMASK, bidx, off);
        const bool take = (ov > bv) || (ov == bv && oi < bidx);
        bv   = take ? ov : bv;
        bidx = take ? oi : bidx;
    }
    if (j == 0) g_last[b] = bidx;
}

// ---------------------------------------------------------------------------
// Main kernel: 128 CTAs x 128 threads, wave-1 (1 CTA/SM), 1 long warp/SMSP:
//   wid 0: fwd  batch 2*bid      wid 1: fwd  batch 2*bid+1
//   wid 2: vit  batch 2*bid      wid 3: vit  batch 2*bid+1
// ---------------------------------------------------------------------------
__global__ __launch_bounds__(128)
void crf_main_kernel(const float* __restrict__ pred,
                     const int*   __restrict__ amask,
                     const float* __restrict__ startv,
                     const float* __restrict__ endv,
                     const float* __restrict__ trans)
{
    const int wib = threadIdx.x >> 5;
    const int j   = threadIdx.x & 31;
    const int wb  = wib & 1;                 // which of the 2 batches
    const int b   = (blockIdx.x << 1) | wb;

    __shared__ __align__(16) float ring[4][512];
    __shared__ __align__(16) float buf[4][2][32];
    __shared__ signed char mkS[2][Sn];
    __shared__ int s_allones[2];

    if (wib < 2) {
        // mask load + all-ones detect (one warp per batch)
        const int* am = amask + (size_t)b * Sn;
        int okv = 1;
        for (int t = j; t < Sn; t += 32) {
            const int mv = am[t];
            mkS[wb][t] = (signed char)mv;
            okv &= (mv == 1);
        }
        const bool ao = __all_sync(FULLMASK, okv != 0);
        if (j == 0) s_allones[wb] = ao ? 1 : 0;
    }
    __syncthreads();

    const float* em = pred + (size_t)b * Sn * Tn;
    float* bufw  = &buf[wib][0][0];
    float* ringw = &ring[wib][0];

    if (wib < 2) {
        if (s_allones[wb])
            fwd_loop<true >(em, j, bufw, ringw, mkS[wb], startv, endv, trans, b);
        else
            fwd_loop<false>(em, j, bufw, ringw, mkS[wb], startv, endv, trans, b);
    } else {
        if (s_allones[wb])
            vit_loop<true >(em, j, bufw, ringw, mkS[wb], startv, endv, trans, b);
        else
            vit_loop<false>(em, j, bufw, ringw, mkS[wb], startv, endv, trans, b);
    }
}

// ---------------------------------------------------------------------------
// Backtrace phase 1 (+ numerator blocks): blocks 0..1023 compute per-chunk
// tag maps; blocks 1024..1087 compute the numerator (4 batches each).
// ---------------------------------------------------------------------------
__global__ __launch_bounds__(128)
void bt_phase1(const float* __restrict__ pred,
               const int*   __restrict__ amask,
               const int*   __restrict__ labels,
               const float* __restrict__ startv,
               const float* __restrict__ endv,
               const float* __restrict__ trans)
{
    const int wib  = threadIdx.x >> 5;
    const int lane = threadIdx.x & 31;

    if (blockIdx.x >= (Bn * NCH) / 4) {
        // ------- Numerator: one warp per batch ------------------------------
        const int b = ((int)blockIdx.x - (Bn * NCH) / 4) * 4 + wib;
        const float* em = pred + (size_t)b * Sn * Tn;
        const int* lab = labels + (size_t)b * Sn;
        const int* am  = amask  + (size_t)b * Sn;
        float sum = 0.f;
        int   msum = 0;
        for (int t = lane; t < Sn; t += 32) {
            const int mt = am[t];
            msum += mt;
            const int tg = lab[t];
            if (t == 0) {
                sum += startv[tg] + em[tg];
            } else {
                const int tp = lab[t - 1];
                sum += (trans[tp * Tn + tg] + em[(size_t)t * Tn + tg]) * (float)mt;
            }
        }
        #pragma unroll
        for (int off = 16; off; off >>= 1) {
            sum  += __shfl_xor_sync(FULLMASK, sum, off);
            msum += __shfl_xor_sync(FULLMASK, msum, off);
        }
        if (lane == 0) {
            const int se = msum - 1;
            const int lt = lab[se];
            g_num[b] = sum + endv[lt];
        }
        return;
    }

    const int gw = (blockIdx.x << 2) | wib;       // 0 .. Bn*NCH-1
    const int b = gw >> 6;
    const int c = gw & 63;
    const int lo = c * 32;
    int hi = lo + 31; if (hi > Sn - 2) hi = Sn - 2;
    const int n = hi - lo + 1;

    __shared__ __align__(16) unsigned char sm[4][32 * Tn];
    unsigned char* S = sm[wib];
    const uint32_t* src = (const uint32_t*)(g_hist + ((size_t)b * (Sn - 1) + lo) * Tn);
    uint32_t* dst = (uint32_t*)S;
    for (int i = lane; i < n * 8; i += 32) dst[i] = src[i];
    __syncwarp();

    int tag = lane;
    for (int k = n - 1; k >= 0; --k) tag = S[k * Tn + tag];
    g_map[b][c][lane] = (unsigned char)tag;
}

// ---------------------------------------------------------------------------
// Backtrace phase 2: per batch, compose the 64 chunk maps from the top.
// Block 64 computes the loss (g_num/g_den are complete after bt_phase1).
// ---------------------------------------------------------------------------
__global__ __launch_bounds__(128)
void bt_phase2(float* __restrict__ out)
{
    if (blockIdx.x == Bn / 4) {
        // ------- Loss: -mean(num - den) -------------------------------------
        __shared__ float red[128];
        const int t = threadIdx.x;
        red[t] = (g_num[t] - g_den[t]) + (g_num[t + 128] - g_den[t + 128]);
        __syncthreads();
        #pragma unroll
        for (int off = 64; off; off >>= 1) {
            if (t < off) red[t] += red[t + off];
            __syncthreads();
        }
        if (t == 0) out[(size_t)Bn * Sn] = -(red[0] / (float)Bn);
        return;
    }

    const int wib  = threadIdx.x >> 5;
    const int lane = threadIdx.x & 31;
    const int b = (blockIdx.x << 2) | wib;

    __shared__ __align__(16) unsigned char sm[4][NCH * Tn];
    __shared__ unsigned char se[4][NCH];
    unsigned char* S = sm[wib];
    const uint32_t* src = (const uint32_t*)&g_map[b][0][0];
    uint32_t* dst = (uint32_t*)S;
    for (int i = lane; i < NCH * Tn / 4; i += 32) dst[i] = src[i];
    __syncwarp();

    if (lane == 0) {
        int e = g_last[b];
        out[(size_t)b * Sn + (Sn - 1)] = (float)e;
        for (int c = NCH - 1; c >= 0; --c) {
            se[wib][c] = (unsigned char)e;   // entry tag for chunk c
            e = S[c * Tn + e];               // exit = map[entry]
        }
    }
    __syncwarp();
    for (int c = lane; c < NCH; c += 32) g_ent[b][c] = se[wib][c];
}

// ---------------------------------------------------------------------------
// Backtrace phase 3: re-chase each chunk from its entry tag; coalesced write.
// ---------------------------------------------------------------------------
__global__ __launch_bounds__(128)
void bt_phase3(float* __restrict__ out)
{
    const int wib  = threadIdx.x >> 5;
    const int lane = threadIdx.x & 31;
    const int gw = (blockIdx.x << 2) | wib;
    const int b = gw >> 6;
    const int c = gw & 63;
    const int lo = c * 32;
    int hi = lo + 31; if (hi > Sn - 2) hi = Sn - 2;
    const int n = hi - lo + 1;

    __shared__ __align__(16) unsigned char sm[4][32 * Tn];
    __shared__ unsigned char stag[4][32];
    unsigned char* S = sm[wib];
    const uint32_t* src = (const uint32_t*)(g_hist + ((size_t)b * (Sn - 1) + lo) * Tn);
    uint32_t* dst = (uint32_t*)S;
    for (int i = lane; i < n * 8; i += 32) dst[i] = src[i];
    __syncwarp();

    if (lane == 0) {
        int tag = g_ent[b][c];
        for (int k = n - 1; k >= 0; --k) {
            tag = S[k * Tn + tag];
            stag[wib][k] = (unsigned char)tag;
        }
    }
    __syncwarp();
    if (lane < n) out[(size_t)b * Sn + lo + lane] = (float)stag[wib][lane];
}

extern "C" void kernel_launch(void* const* d_in, const int* in_sizes, int n_in,
                              void* d_out, int out_size)
{
    const float* pred   = (const float*)d_in[0];
    const int*   amask  = (const int*)  d_in[1];
    const int*   labels = (const int*)  d_in[2];
    const float* startv = (const float*)d_in[3];
    const float* endv   = (const float*)d_in[4];
    const float* trans  = (const float*)d_in[5];
    float* out = (float*)d_out;

    crf_main_kernel<<<128, 128>>>(pred, amask, startv, endv, trans);
    bt_phase1<<<(Bn * NCH) / 4 + Bn / 4, 128>>>(pred, amask, labels, startv, endv, trans);
    bt_phase2<<<Bn / 4 + 1, 128>>>(out);
    bt_phase3<<<(Bn * NCH) / 4, 128>>>(out);
}

// round 16
// speedup vs baseline: 1.3512x; 1.0162x over previous
#include <cuda_runtime.h>
#include <cuda_bf16.h>
#include <cstdint>

#define Bn 256
#define Sn 2048
#define Tn 32
#define NCH 64
#define NR  512               // 512 hist words per (batch, tag): word r = steps t=4r+1..4r+4
#define FULLMASK 0xffffffffu
#define LOG32F 3.4657359027997265f

// Scratch (device globals are the sanctioned scratch mechanism)
__device__ uint32_t g_hist4[(size_t)Bn * NR * Tn];  // packed backpointers, 16.8 MB
__device__ unsigned char g_map[Bn][NCH][Tn];        // chunk tag maps
__device__ float g_den[Bn];
__device__ float g_num[Bn];
__device__ int   g_last[Bn];

// ---- packed f32x2 helpers (Blackwell) -------------------------------------
__device__ __forceinline__ float2 fadd2(float2 a, float2 b) {
    union { float2 f; unsigned long long u; } A, B, R;
    A.f = a; B.f = b;
    asm("add.rn.f32x2 %0, %1, %2;" : "=l"(R.u) : "l"(A.u), "l"(B.u));
    return R.f;
}
__device__ __forceinline__ float2 ffma2(float2 a, float2 b, float2 c) {
    union { float2 f; unsigned long long u; } A, B, C, R;
    A.f = a; B.f = b; C.f = c;
    asm("fma.rn.f32x2 %0, %1, %2, %3;" : "=l"(R.u) : "l"(A.u), "l"(B.u), "l"(C.u));
    return R.f;
}

// ---- cp.async helpers ------------------------------------------------------
__device__ __forceinline__ uint32_t smem_u32(const void* p) {
    return (uint32_t)__cvta_generic_to_shared(p);
}
__device__ __forceinline__ void cp16(uint32_t d, const void* s) {
    asm volatile("cp.async.cg.shared.global [%0], [%1], 16;" :: "r"(d), "l"(s));
}
#define CP_COMMIT() asm volatile("cp.async.commit_group;")
#define CP_WAIT2()  asm volatile("cp.async.wait_group 2;")
#define CP_WAIT0()  asm volatile("cp.async.wait_group 0;")

// Ring: 4 slots x 512 B per warp. Slot (r&3) holds em rows 4r+1..4r+4
// (for the clamped last group r=511: rows 2044..2047).

// ---------------------------------------------------------------------------
// Forward algorithm, linear domain with deferred renorm.
// Renorm at t == 15 mod 16 exactly as the verified r13/r15 kernels.
// ---------------------------------------------------------------------------
template<bool AM>
__device__ __forceinline__ void fwd_loop(const float* __restrict__ em, int j,
                                         float* __restrict__ bufw,
                                         float* __restrict__ ringw,
                                         const signed char* __restrict__ mk,
                                         const float* __restrict__ startv,
                                         const float* __restrict__ endv,
                                         const float* __restrict__ trans,
                                         int b)
{
    float2 tc2[16];
    #pragma unroll
    for (int k = 0; k < 16; ++k) {
        float2 p;
        p.x = __expf(trans[(2 * k + 0) * Tn + j]) * 0.03125f;
        p.y = __expf(trans[(2 * k + 1) * Tn + j]) * 0.03125f;
        tc2[k] = p;
    }

    const uint32_t rbase = smem_u32(ringw);
    #pragma unroll
    for (int r = 0; r < 3; ++r) {
        cp16(rbase + (uint32_t)(r * 512 + j * 16),
             em + (size_t)(4 * r + 1) * Tn + j * 4);
        CP_COMMIT();
    }

    float s  = __expf(startv[j] + em[j]);
    float Lr = 0.f;
    int   nm = 0;

    bufw[j] = s;                     // slot 0 holds state at t=0
    __syncwarp();

    auto fstep = [&](int t, float ee, bool renorm) {
        const float* sb = bufw + ((t + 1) & 1) * 32;   // state t-1
        float2 a0 = {0.f, 0.f}, a1 = {0.f, 0.f}, a2 = {0.f, 0.f}, a3 = {0.f, 0.f};
        #pragma unroll
        for (int k = 0; k < 4; ++k) {
            const float4 qa = *(const float4*)(sb + 8 * k);
            const float4 qb = *(const float4*)(sb + 8 * k + 4);
            a0 = ffma2(make_float2(qa.x, qa.y), tc2[4 * k + 0], a0);
            a1 = ffma2(make_float2(qa.z, qa.w), tc2[4 * k + 1], a1);
            a2 = ffma2(make_float2(qb.x, qb.y), tc2[4 * k + 2], a2);
            a3 = ffma2(make_float2(qb.z, qb.w), tc2[4 * k + 3], a3);
        }
        const float2 a01 = fadd2(a0, a1);
        const float2 a23 = fadd2(a2, a3);
        const float2 aa  = fadd2(a01, a23);
        const float ns = (aa.x + aa.y) * ee;
        if (AM) {
            s = ns;
        } else {
            const int m_ = mk[t];
            s = m_ ? ns : s;
            nm += (m_ != 0);
        }
        if (renorm) {                                  // t % 16 == 15 (pre-store)
            const float r_ = __shfl_sync(FULLMASK, s, 0);
            const float rr = __frcp_rn(r_);
            s *= rr;
            Lr -= __logf(rr);
        }
        bufw[(t & 1) * 32 + j] = s;
        __syncwarp();
    };

    #pragma unroll 1
    for (int r = 0; r < 511; ++r) {                    // t = 4r+1 .. 4r+4
        CP_WAIT2();
        const float* grp = ringw + (r & 3) * 128;
        const float ee0 = __expf(grp[0 * 32 + j]);
        const float ee1 = __expf(grp[1 * 32 + j]);
        const float ee2 = __expf(grp[2 * 32 + j]);
        const float ee3 = __expf(grp[3 * 32 + j]);
        fstep(4 * r + 1, ee0, false);
        fstep(4 * r + 2, ee1, false);
        fstep(4 * r + 3, ee2, (r & 3) == 3);           // t=16m+15
        fstep(4 * r + 4, ee3, false);
        const int rp  = r + 3;
        const int rpc = (rp < 511) ? rp : 511;
        const int src = (rpc == 511) ? 2044 : (4 * rpc + 1);
        cp16(rbase + (uint32_t)((rpc & 3) * 512 + j * 16),
             em + (size_t)src * Tn + j * 4);
        CP_COMMIT();
    }
    // tail t = 2045..2047 : slot 3 holds rows 2044..2047 at u=0..3
    CP_WAIT0();
    __syncwarp();
    {
        const float* grp = ringw + 3 * 128;
        const float ee1 = __expf(grp[1 * 32 + j]);     // row 2045
        const float ee2 = __expf(grp[2 * 32 + j]);     // row 2046
        const float ee3 = __expf(grp[3 * 32 + j]);     // row 2047
        fstep(2045, ee1, false);
        fstep(2046, ee2, false);
        fstep(2047, ee3, true);                        // 2047 % 16 == 15
    }

    if (AM) nm = Sn - 1;
    float v = s * __expf(endv[j]);
    #pragma unroll
    for (int off = 16; off; off >>= 1)
        v += __shfl_xor_sync(FULLMASK, v, off);
    if (j == 0) g_den[b] = (float)nm * LOG32F + Lr + __logf(v);
}

// ---------------------------------------------------------------------------
// Viterbi: tournament argmax split across the sync (r15-verified semantics),
// backpointers packed 4 steps per uint32 word (word r = t=4r+1..4r+4).
// ---------------------------------------------------------------------------
template<bool AM>
__device__ __forceinline__ void vit_loop(const float* __restrict__ em, int j,
                                         float* __restrict__ bufw,
                                         float* __restrict__ ringw,
                                         const signed char* __restrict__ mk,
                                         const float* __restrict__ startv,
                                         const float* __restrict__ endv,
                                         const float* __restrict__ trans,
                                         int b)
{
    float2 tc2[16];
    #pragma unroll
    for (int k = 0; k < 16; ++k) {
        float2 p;
        p.x = trans[(2 * k + 0) * Tn + j];
        p.y = trans[(2 * k + 1) * Tn + j];
        tc2[k] = p;
    }

    const uint32_t rbase = smem_u32(ringw);
    #pragma unroll
    for (int r = 0; r < 3; ++r) {
        cp16(rbase + (uint32_t)(r * 512 + j * 16),
             em + (size_t)(4 * r + 1) * Tn + j * 4);
        CP_COMMIT();
    }

    float v = startv[j] + em[j];
    uint32_t* hw = g_hist4 + (size_t)b * NR * Tn;

    bufw[j] = v;                     // slot 0 holds state at t=0
    __syncwarp();

    auto step = [&](int t, float emt, uint32_t& word, int sh) {
        const float* vb = bufw + ((t + 1) & 1) * 32;   // state t-1

        // ---- value phase + L1 indices -------------------------------------
        float tv[16]; int ti[16];
        #pragma unroll
        for (int k = 0; k < 8; ++k) {
            const float4 q = *(const float4*)(vb + 4 * k);
            const float2 p0 = fadd2(make_float2(q.x, q.y), tc2[2 * k + 0]);
            const float2 p1 = fadd2(make_float2(q.z, q.w), tc2[2 * k + 1]);
            const bool s0 = p0.y > p0.x;
            tv[2 * k + 0] = fmaxf(p0.x, p0.y);
            ti[2 * k + 0] = s0 ? (4 * k + 1) : (4 * k + 0);
            const bool s1 = p1.y > p1.x;
            tv[2 * k + 1] = fmaxf(p1.x, p1.y);
            ti[2 * k + 1] = s1 ? (4 * k + 3) : (4 * k + 2);
        }
        float uv[8];
        #pragma unroll
        for (int i = 0; i < 8; ++i) uv[i] = fmaxf(tv[2 * i], tv[2 * i + 1]);
        float wv[4];
        #pragma unroll
        for (int i = 0; i < 4; ++i) wv[i] = fmaxf(uv[2 * i], uv[2 * i + 1]);
        const float xv0 = fmaxf(wv[0], wv[1]);
        const float xv1 = fmaxf(wv[2], wv[3]);
        const float m   = fmaxf(xv0, xv1);

        const float nv = m + emt;
        int m_ = 1;
        if (!AM) m_ = mk[t];
        v = m_ ? nv : v;
        bufw[(t & 1) * 32 + j] = v;          // commit state EARLY
        __syncwarp();

        // ---- index phase (post-sync) --------------------------------------
        int ui[8];
        #pragma unroll
        for (int i = 0; i < 8; ++i)
            ui[i] = (tv[2 * i + 1] > tv[2 * i]) ? ti[2 * i + 1] : ti[2 * i];
        int wi[4];
        #pragma unroll
        for (int i = 0; i < 4; ++i)
            wi[i] = (uv[2 * i + 1] > uv[2 * i]) ? ui[2 * i + 1] : ui[2 * i];
        const int xi0 = (wv[1] > wv[0]) ? wi[1] : wi[0];
        const int xi1 = (wv[3] > wv[2]) ? wi[3] : wi[2];
        const int bi  = (xv1 > xv0) ? xi1 : xi0;
        const int bp  = m_ ? bi : j;
        word |= (uint32_t)bp << sh;
    };

    #pragma unroll 1
    for (int r = 0; r < 511; ++r) {                    // t = 4r+1 .. 4r+4
        CP_WAIT2();
        const float* grp = ringw + (r & 3) * 128;
        const float e0 = grp[0 * 32 + j];
        const float e1 = grp[1 * 32 + j];
        const float e2 = grp[2 * 32 + j];
        const float e3 = grp[3 * 32 + j];
        uint32_t word = 0;
        step(4 * r + 1, e0, word, 0);
        step(4 * r + 2, e1, word, 8);
        step(4 * r + 3, e2, word, 16);
        step(4 * r + 4, e3, word, 24);
        hw[(size_t)r * Tn + j] = word;
        const int rp  = r + 3;
        const int rpc = (rp < 511) ? rp : 511;
        const int src = (rpc == 511) ? 2044 : (4 * rpc + 1);
        cp16(rbase + (uint32_t)((rpc & 3) * 512 + j * 16),
             em + (size_t)src * Tn + j * 4);
        CP_COMMIT();
    }
    // tail t = 2045..2047 (word r=511, bytes 0..2; byte 3 = 0)
    CP_WAIT0();
    __syncwarp();
    {
        const float* grp = ringw + 3 * 128;
        const float e1 = grp[1 * 32 + j];
        const float e2 = grp[2 * 32 + j];
        const float e3 = grp[3 * 32 + j];
        uint32_t word = 0;
        step(2045, e1, word, 0);
        step(2046, e2, word, 8);
        step(2047, e3, word, 16);
        hw[(size_t)511 * Tn + j] = word;
    }

    // last_tag = argmax_j (v_j + end_j), lowest index on ties
    float bv = v + endv[j];
    int   bidx = j;
    #pragma unroll
    for (int off = 16; off; off >>= 1) {
        const float ov = __shfl_xor_sync(FULLMASK, bv, off);
        const int   oi = __shfl_xor_sync(FULLMASK, bidx, off);
        const bool take = (ov > bv) || (ov == bv && oi < bidx);
        bv   = take ? ov : bv;
        bidx = take ? oi : bidx;
    }
    if (j == 0) g_last[b] = bidx;
}

// ---------------------------------------------------------------------------
// Main kernel: 128 CTAs x 128 threads, wave-1 (1 CTA/SM), 1 long warp/SMSP:
//   wid 0: fwd  batch 2*bid      wid 1: fwd  batch 2*bid+1
//   wid 2: vit  batch 2*bid      wid 3: vit  batch 2*bid+1
// ---------------------------------------------------------------------------
__global__ __launch_bounds__(128)
void crf_main_kernel(const float* __restrict__ pred,
                     const int*   __restrict__ amask,
                     const float* __restrict__ startv,
                     const float* __restrict__ endv,
                     const float* __restrict__ trans)
{
    const int wib = threadIdx.x >> 5;
    const int j   = threadIdx.x & 31;
    const int wb  = wib & 1;                 // which of the 2 batches
    const int b   = (blockIdx.x << 1) | wb;

    __shared__ __align__(16) float ring[4][512];
    __shared__ __align__(16) float buf[4][2][32];
    __shared__ signed char mkS[2][Sn];
    __shared__ int s_allones[2];

    if (wib < 2) {
        // mask load + all-ones detect (one warp per batch)
        const int* am = amask + (size_t)b * Sn;
        int okv = 1;
        for (int t = j; t < Sn; t += 32) {
            const int mv = am[t];
            mkS[wb][t] = (signed char)mv;
            okv &= (mv == 1);
        }
        const bool ao = __all_sync(FULLMASK, okv != 0);
        if (j == 0) s_allones[wb] = ao ? 1 : 0;
    }
    __syncthreads();

    const float* em = pred + (size_t)b * Sn * Tn;
    float* bufw  = &buf[wib][0][0];
    float* ringw = &ring[wib][0];

    if (wib < 2) {
        if (s_allones[wb])
            fwd_loop<true >(em, j, bufw, ringw, mkS[wb], startv, endv, trans, b);
        else
            fwd_loop<false>(em, j, bufw, ringw, mkS[wb], startv, endv, trans, b);
    } else {
        if (s_allones[wb])
            vit_loop<true >(em, j, bufw, ringw, mkS[wb], startv, endv, trans, b);
        else
            vit_loop<false>(em, j, bufw, ringw, mkS[wb], startv, endv, trans, b);
    }
}

// ---------------------------------------------------------------------------
// bt_phase1: blocks 0..4095 compute per-chunk tag maps from packed hist;
// blocks 4096..4159 compute the numerator (4 batches each).
// Chunk c covers idx 32c..32c+31 == words 8c..8c+7 (byte u = idx&3).
// ---------------------------------------------------------------------------
__global__ __launch_bounds__(128)
void bt_phase1(const float* __restrict__ pred,
               const int*   __restrict__ amask,
               const int*   __restrict__ labels,
               const float* __restrict__ startv,
               const float* __restrict__ endv,
               const float* __restrict__ trans)
{
    const int wib  = threadIdx.x >> 5;
    const int lane = threadIdx.x & 31;

    if (blockIdx.x >= (Bn * NCH) / 4) {
        // ------- Numerator: one warp per batch ------------------------------
        const int b = ((int)blockIdx.x - (Bn * NCH) / 4) * 4 + wib;
        const float* em = pred + (size_t)b * Sn * Tn;
        const int* lab = labels + (size_t)b * Sn;
        const int* am  = amask  + (size_t)b * Sn;
        float sum = 0.f;
        int   msum = 0;
        for (int t = lane; t < Sn; t += 32) {
            const int mt = am[t];
            msum += mt;
            const int tg = lab[t];
            if (t == 0) {
                sum += startv[tg] + em[tg];
            } else {
                const int tp = lab[t - 1];
                sum += (trans[tp * Tn + tg] + em[(size_t)t * Tn + tg]) * (float)mt;
            }
        }
        #pragma unroll
        for (int off = 16; off; off >>= 1) {
            sum  += __shfl_xor_sync(FULLMASK, sum, off);
            msum += __shfl_xor_sync(FULLMASK, msum, off);
        }
        if (lane == 0) {
            const int se = msum - 1;
            const int lt = lab[se];
            g_num[b] = sum + endv[lt];
        }
        return;
    }

    const int gw = (blockIdx.x << 2) | wib;       // 0 .. Bn*NCH-1
    const int b = gw >> 6;
    const int c = gw & 63;
    const int n = (c == 63) ? 31 : 32;            // idx max = 2046

    __shared__ __align__(16) uint32_t S4[4][8 * Tn];
    uint32_t* Sw = S4[wib];
    const uint32_t* hsrc = g_hist4 + ((size_t)b * NR + 8 * c) * Tn;
    for (int i = lane; i < 8 * Tn; i += 32) Sw[i] = hsrc[i];
    __syncwarp();

    int tag = lane;
    #pragma unroll
    for (int k = 31; k >= 0; --k) {
        if (k < n) {
            const uint32_t w = Sw[(k >> 2) * Tn + tag];
            tag = (int)((w >> ((k & 3) * 8)) & 255u);
        }
    }
    g_map[b][c][lane] = (unsigned char)tag;
}

// ---------------------------------------------------------------------------
// bt_phase3: blocks 0..4095 decode one chunk each (entry tag derived locally
// by composing the suffix of chunk maps -- replaces bt_phase2); block 4096
// computes the loss.
// ---------------------------------------------------------------------------
__global__ __launch_bounds__(128)
void bt_phase3(float* __restrict__ out)
{
    if (blockIdx.x == (Bn * NCH) / 4) {
        // ------- Loss: -mean(num - den) -------------------------------------
        __shared__ float red[128];
        const int t = threadIdx.x;
        red[t] = (g_num[t] - g_den[t]) + (g_num[t + 128] - g_den[t + 128]);
        __syncthreads();
        #pragma unroll
        for (int off = 64; off; off >>= 1) {
            if (t < off) red[t] += red[t + off];
            __syncthreads();
        }
        if (t == 0) out[(size_t)Bn * Sn] = -(red[0] / (float)Bn);
        return;
    }

    const int wib  = threadIdx.x >> 5;
    const int lane = threadIdx.x & 31;
    const int gw = (blockIdx.x << 2) | wib;
    const int b = gw >> 6;
    const int c = gw & 63;
    const int lo = c * 32;
    const int n = (c == 63) ? 31 : 32;

    __shared__ __align__(16) uint32_t S4[4][8 * Tn];
    __shared__ __align__(16) uint32_t Mw[4][(NCH * Tn) / 4];

    // stage this chunk's packed hist words
    uint32_t* Sw = S4[wib];
    const uint32_t* hsrc = g_hist4 + ((size_t)b * NR + 8 * c) * Tn;
    for (int i = lane; i < 8 * Tn; i += 32) Sw[i] = hsrc[i];

    // stage suffix maps c..63 (rows of 32 bytes = 8 words each)
    uint32_t* Mq = Mw[wib];
    const int nrows = NCH - c;
    const uint32_t* msrc = (const uint32_t*)&g_map[b][c][0];
    for (int i = lane; i < nrows * 8; i += 32) Mq[i] = msrc[i];
    __syncwarp();

    // entry tag: compose maps 63 -> c+1 starting from g_last (all lanes, bcast)
    int e = g_last[b];
    const unsigned char* Mb = (const unsigned char*)Mq;
    for (int cc = 63; cc > c; --cc)
        e = Mb[(cc - c) * Tn + e];

    // decode: chase through the chunk; lane L captures position lo+L
    int tag = e;
    int cur = 0;
    #pragma unroll
    for (int k = 31; k >= 0; --k) {
        if (k < n) {
            const uint32_t w = Sw[(k >> 2) * Tn + tag];
            tag = (int)((w >> ((k & 3) * 8)) & 255u);
            if (k == lane) cur = tag;
        }
    }
    if (lane < n) out[(size_t)b * Sn + lo + lane] = (float)cur;
    if (c == 63 && lane == 31) out[(size_t)b * Sn + (Sn - 1)] = (float)g_last[b];
}

extern "C" void kernel_launch(void* const* d_in, const int* in_sizes, int n_in,
                              void* d_out, int out_size)
{
    const float* pred   = (const float*)d_in[0];
    const int*   amask  = (const int*)  d_in[1];
    const int*   labels = (const int*)  d_in[2];
    const float* startv = (const float*)d_in[3];
    const float* endv   = (const float*)d_in[4];
    const float* trans  = (const float*)d_in[5];
    float* out = (float*)d_out;

    crf_main_kernel<<<128, 128>>>(pred, amask, startv, endv, trans);
    bt_phase1<<<(Bn * NCH) / 4 + Bn / 4, 128>>>(pred, amask, labels, startv, endv, trans);
    bt_phase3<<<(Bn * NCH) / 4 + 1, 128>>>(out);
}

// round 17
// speedup vs baseline: 1.4369x; 1.0635x over previous
#include <cuda_runtime.h>
#include <cuda_bf16.h>
#include <cstdint>

#define Bn 256
#define Sn 2048
#define Tn 32
#define NCH 64
#define NR  512               // 512 hist words per (batch, tag): word r = steps t=4r+1..4r+4
#define FULLMASK 0xffffffffu
#define LOG32F 3.4657359027997265f

// Scratch (device globals are the sanctioned scratch mechanism)
__device__ uint32_t g_hist4[(size_t)Bn * NR * Tn];  // packed backpointers, 16.8 MB
__device__ unsigned char g_map[Bn][NCH][Tn];        // chunk tag maps
__device__ float g_den[Bn];
__device__ float g_num[Bn];
__device__ int   g_last[Bn];

// ---- packed f32x2 helpers (Blackwell) -------------------------------------
__device__ __forceinline__ float2 fadd2(float2 a, float2 b) {
    union { float2 f; unsigned long long u; } A, B, R;
    A.f = a; B.f = b;
    asm("add.rn.f32x2 %0, %1, %2;" : "=l"(R.u) : "l"(A.u), "l"(B.u));
    return R.f;
}
__device__ __forceinline__ float2 ffma2(float2 a, float2 b, float2 c) {
    union { float2 f; unsigned long long u; } A, B, C, R;
    A.f = a; B.f = b; C.f = c;
    asm("fma.rn.f32x2 %0, %1, %2, %3;" : "=l"(R.u) : "l"(A.u), "l"(B.u), "l"(C.u));
    return R.f;
}

// ---- cp.async helpers ------------------------------------------------------
__device__ __forceinline__ uint32_t smem_u32(const void* p) {
    return (uint32_t)__cvta_generic_to_shared(p);
}
__device__ __forceinline__ void cp16(uint32_t d, const void* s) {
    asm volatile("cp.async.cg.shared.global [%0], [%1], 16;" :: "r"(d), "l"(s));
}
#define CP_COMMIT() asm volatile("cp.async.commit_group;")
#define CP_WAIT2()  asm volatile("cp.async.wait_group 2;")
#define CP_WAIT0()  asm volatile("cp.async.wait_group 0;")

// Ring: 4 slots x 512 B per warp. Slot (r&3) holds em rows 4r+1..4r+4
// (for the clamped last group r=511: rows 2044..2047).
// NOTE (sync-free exchange): within a non-divergent warp, STS -> LDS to the
// same SMEM region is serviced in order by the per-warp MIO queue; ptxas
// keeps the order (must-alias). The per-step __syncwarp is therefore elided.

// ---------------------------------------------------------------------------
// Forward algorithm, linear domain with deferred renorm.
// Renorm at t == 15 mod 16 exactly as the verified r13/r16 kernels.
// ---------------------------------------------------------------------------
template<bool AM>
__device__ __forceinline__ void fwd_loop(const float* __restrict__ em, int j,
                                         float* __restrict__ bufw,
                                         float* __restrict__ ringw,
                                         const signed char* __restrict__ mk,
                                         const float* __restrict__ startv,
                                         const float* __restrict__ endv,
                                         const float* __restrict__ trans,
                                         int b)
{
    float2 tc2[16];
    #pragma unroll
    for (int k = 0; k < 16; ++k) {
        float2 p;
        p.x = __expf(trans[(2 * k + 0) * Tn + j]) * 0.03125f;
        p.y = __expf(trans[(2 * k + 1) * Tn + j]) * 0.03125f;
        tc2[k] = p;
    }

    const uint32_t rbase = smem_u32(ringw);
    #pragma unroll
    for (int r = 0; r < 3; ++r) {
        cp16(rbase + (uint32_t)(r * 512 + j * 16),
             em + (size_t)(4 * r + 1) * Tn + j * 4);
        CP_COMMIT();
    }

    float s  = __expf(startv[j] + em[j]);
    float Lr = 0.f;
    int   nm = 0;

    bufw[j] = s;                     // slot 0 holds state at t=0

    auto fstep = [&](int t, float ee, bool renorm) {
        const float* sb = bufw + ((t + 1) & 1) * 32;   // state t-1
        float2 a0 = {0.f, 0.f}, a1 = {0.f, 0.f}, a2 = {0.f, 0.f}, a3 = {0.f, 0.f};
        #pragma unroll
        for (int k = 0; k < 4; ++k) {
            const float4 qa = *(const float4*)(sb + 8 * k);
            const float4 qb = *(const float4*)(sb + 8 * k + 4);
            a0 = ffma2(make_float2(qa.x, qa.y), tc2[4 * k + 0], a0);
            a1 = ffma2(make_float2(qa.z, qa.w), tc2[4 * k + 1], a1);
            a2 = ffma2(make_float2(qb.x, qb.y), tc2[4 * k + 2], a2);
            a3 = ffma2(make_float2(qb.z, qb.w), tc2[4 * k + 3], a3);
        }
        const float2 a01 = fadd2(a0, a1);
        const float2 a23 = fadd2(a2, a3);
        const float2 aa  = fadd2(a01, a23);
        const float ns = (aa.x + aa.y) * ee;
        if (AM) {
            s = ns;
        } else {
            const int m_ = mk[t];
            s = m_ ? ns : s;
            nm += (m_ != 0);
        }
        if (renorm) {                                  // t % 16 == 15 (pre-store)
            const float r_ = __shfl_sync(FULLMASK, s, 0);
            const float rr = __frcp_rn(r_);
            s *= rr;
            Lr -= __logf(rr);
        }
        bufw[(t & 1) * 32 + j] = s;
    };

    #pragma unroll 1
    for (int r = 0; r < 511; ++r) {                    // t = 4r+1 .. 4r+4
        CP_WAIT2();
        const float* grp = ringw + (r & 3) * 128;
        const float ee0 = __expf(grp[0 * 32 + j]);
        const float ee1 = __expf(grp[1 * 32 + j]);
        const float ee2 = __expf(grp[2 * 32 + j]);
        const float ee3 = __expf(grp[3 * 32 + j]);
        fstep(4 * r + 1, ee0, false);
        fstep(4 * r + 2, ee1, false);
        fstep(4 * r + 3, ee2, (r & 3) == 3);           // t=16m+15
        fstep(4 * r + 4, ee3, false);
        const int rp  = r + 3;
        const int rpc = (rp < 511) ? rp : 511;
        const int src = (rpc == 511) ? 2044 : (4 * rpc + 1);
        cp16(rbase + (uint32_t)((rpc & 3) * 512 + j * 16),
             em + (size_t)src * Tn + j * 4);
        CP_COMMIT();
    }
    // tail t = 2045..2047 : slot 3 holds rows 2044..2047 at u=0..3
    CP_WAIT0();
    {
        const float* grp = ringw + 3 * 128;
        const float ee1 = __expf(grp[1 * 32 + j]);     // row 2045
        const float ee2 = __expf(grp[2 * 32 + j]);     // row 2046
        const float ee3 = __expf(grp[3 * 32 + j]);     // row 2047
        fstep(2045, ee1, false);
        fstep(2046, ee2, false);
        fstep(2047, ee3, true);                        // 2047 % 16 == 15
    }

    if (AM) nm = Sn - 1;
    float v = s * __expf(endv[j]);
    #pragma unroll
    for (int off = 16; off; off >>= 1)
        v += __shfl_xor_sync(FULLMASK, v, off);
    if (j == 0) g_den[b] = (float)nm * LOG32F + Lr + __logf(v);
}

// ---------------------------------------------------------------------------
// Viterbi: tournament argmax split around the state commit (r15/r16-verified
// semantics), backpointers packed 4 steps per uint32 word.
// ---------------------------------------------------------------------------
template<bool AM>
__device__ __forceinline__ void vit_loop(const float* __restrict__ em, int j,
                                         float* __restrict__ bufw,
                                         float* __restrict__ ringw,
                                         const signed char* __restrict__ mk,
                                         const float* __restrict__ startv,
                                         const float* __restrict__ endv,
                                         const float* __restrict__ trans,
                                         int b)
{
    float2 tc2[16];
    #pragma unroll
    for (int k = 0; k < 16; ++k) {
        float2 p;
        p.x = trans[(2 * k + 0) * Tn + j];
        p.y = trans[(2 * k + 1) * Tn + j];
        tc2[k] = p;
    }

    const uint32_t rbase = smem_u32(ringw);
    #pragma unroll
    for (int r = 0; r < 3; ++r) {
        cp16(rbase + (uint32_t)(r * 512 + j * 16),
             em + (size_t)(4 * r + 1) * Tn + j * 4);
        CP_COMMIT();
    }

    float v = startv[j] + em[j];
    uint32_t* hw = g_hist4 + (size_t)b * NR * Tn;

    bufw[j] = v;                     // slot 0 holds state at t=0

    auto step = [&](int t, float emt, uint32_t& word, int sh) {
        const float* vb = bufw + ((t + 1) & 1) * 32;   // state t-1

        // ---- value phase + L1 indices -------------------------------------
        float tv[16]; int ti[16];
        #pragma unroll
        for (int k = 0; k < 8; ++k) {
            const float4 q = *(const float4*)(vb + 4 * k);
            const float2 p0 = fadd2(make_float2(q.x, q.y), tc2[2 * k + 0]);
            const float2 p1 = fadd2(make_float2(q.z, q.w), tc2[2 * k + 1]);
            const bool s0 = p0.y > p0.x;
            tv[2 * k + 0] = fmaxf(p0.x, p0.y);
            ti[2 * k + 0] = s0 ? (4 * k + 1) : (4 * k + 0);
            const bool s1 = p1.y > p1.x;
            tv[2 * k + 1] = fmaxf(p1.x, p1.y);
            ti[2 * k + 1] = s1 ? (4 * k + 3) : (4 * k + 2);
        }
        float uv[8];
        #pragma unroll
        for (int i = 0; i < 8; ++i) uv[i] = fmaxf(tv[2 * i], tv[2 * i + 1]);
        float wv[4];
        #pragma unroll
        for (int i = 0; i < 4; ++i) wv[i] = fmaxf(uv[2 * i], uv[2 * i + 1]);
        const float xv0 = fmaxf(wv[0], wv[1]);
        const float xv1 = fmaxf(wv[2], wv[3]);
        const float m   = fmaxf(xv0, xv1);

        const float nv = m + emt;
        int m_ = 1;
        if (!AM) m_ = mk[t];
        v = m_ ? nv : v;
        bufw[(t & 1) * 32 + j] = v;          // commit state EARLY

        // ---- index phase (after the commit) -------------------------------
        int ui[8];
        #pragma unroll
        for (int i = 0; i < 8; ++i)
            ui[i] = (tv[2 * i + 1] > tv[2 * i]) ? ti[2 * i + 1] : ti[2 * i];
        int wi[4];
        #pragma unroll
        for (int i = 0; i < 4; ++i)
            wi[i] = (uv[2 * i + 1] > uv[2 * i]) ? ui[2 * i + 1] : ui[2 * i];
        const int xi0 = (wv[1] > wv[0]) ? wi[1] : wi[0];
        const int xi1 = (wv[3] > wv[2]) ? wi[3] : wi[2];
        const int bi  = (xv1 > xv0) ? xi1 : xi0;
        const int bp  = m_ ? bi : j;
        word |= (uint32_t)bp << sh;
    };

    #pragma unroll 1
    for (int r = 0; r < 511; ++r) {                    // t = 4r+1 .. 4r+4
        CP_WAIT2();
        const float* grp = ringw + (r & 3) * 128;
        const float e0 = grp[0 * 32 + j];
        const float e1 = grp[1 * 32 + j];
        const float e2 = grp[2 * 32 + j];
        const float e3 = grp[3 * 32 + j];
        uint32_t word = 0;
        step(4 * r + 1, e0, word, 0);
        step(4 * r + 2, e1, word, 8);
        step(4 * r + 3, e2, word, 16);
        step(4 * r + 4, e3, word, 24);
        hw[(size_t)r * Tn + j] = word;
        const int rp  = r + 3;
        const int rpc = (rp < 511) ? rp : 511;
        const int src = (rpc == 511) ? 2044 : (4 * rpc + 1);
        cp16(rbase + (uint32_t)((rpc & 3) * 512 + j * 16),
             em + (size_t)src * Tn + j * 4);
        CP_COMMIT();
    }
    // tail t = 2045..2047 (word r=511, bytes 0..2; byte 3 = 0)
    CP_WAIT0();
    {
        const float* grp = ringw + 3 * 128;
        const float e1 = grp[1 * 32 + j];
        const float e2 = grp[2 * 32 + j];
        const float e3 = grp[3 * 32 + j];
        uint32_t word = 0;
        step(2045, e1, word, 0);
        step(2046, e2, word, 8);
        step(2047, e3, word, 16);
        hw[(size_t)511 * Tn + j] = word;
    }

    // last_tag = argmax_j (v_j + end_j), lowest index on ties
    float bv = v + endv[j];
    int   bidx = j;
    #pragma unroll
    for (int off = 16; off; off >>= 1) {
        const float ov = __shfl_xor_sync(FULLMASK, bv, off);
        const int   oi = __shfl_xor_sync(FULLMASK, bidx, off);
        const bool take = (ov > bv) || (ov == bv && oi < bidx);
        bv   = take ? ov : bv;
        bidx = take ? oi : bidx;
    }
    if (j == 0) g_last[b] = bidx;
}

// ---------------------------------------------------------------------------
// Main kernel: 128 CTAs x 128 threads, wave-1 (1 CTA/SM), 1 long warp/SMSP:
//   wid 0: fwd  batch 2*bid      wid 1: fwd  batch 2*bid+1
//   wid 2: vit  batch 2*bid      wid 3: vit  batch 2*bid+1
// ---------------------------------------------------------------------------
__global__ __launch_bounds__(128)
void crf_main_kernel(const float* __restrict__ pred,
                     const int*   __restrict__ amask,
                     const float* __restrict__ startv,
                     const float* __restrict__ endv,
                     const float* __restrict__ trans)
{
    const int wib = threadIdx.x >> 5;
    const int j   = threadIdx.x & 31;
    const int wb  = wib & 1;                 // which of the 2 batches
    const int b   = (blockIdx.x << 1) | wb;

    __shared__ __align__(16) float ring[4][512];
    __shared__ __align__(16) float buf[4][2][32];
    __shared__ signed char mkS[2][Sn];
    __shared__ int s_allones[2];

    if (wib < 2) {
        // mask load + all-ones detect (one warp per batch)
        const int* am = amask + (size_t)b * Sn;
        int okv = 1;
        for (int t = j; t < Sn; t += 32) {
            const int mv = am[t];
            mkS[wb][t] = (signed char)mv;
            okv &= (mv == 1);
        }
        const bool ao = __all_sync(FULLMASK, okv != 0);
        if (j == 0) s_allones[wb] = ao ? 1 : 0;
    }
    __syncthreads();

    const float* em = pred + (size_t)b * Sn * Tn;
    float* bufw  = &buf[wib][0][0];
    float* ringw = &ring[wib][0];

    if (wib < 2) {
        if (s_allones[wb])
            fwd_loop<true >(em, j, bufw, ringw, mkS[wb], startv, endv, trans, b);
        else
            fwd_loop<false>(em, j, bufw, ringw, mkS[wb], startv, endv, trans, b);
    } else {
        if (s_allones[wb])
            vit_loop<true >(em, j, bufw, ringw, mkS[wb], startv, endv, trans, b);
        else
            vit_loop<false>(em, j, bufw, ringw, mkS[wb], startv, endv, trans, b);
    }
}

// ---------------------------------------------------------------------------
// bt_phase1: blocks 0..4095 compute per-chunk tag maps from packed hist;
// blocks 4096..4159 compute the numerator (4 batches each).
// Chunk c covers idx 32c..32c+31 == words 8c..8c+7 (byte u = idx&3).
// ---------------------------------------------------------------------------
__global__ __launch_bounds__(128)
void bt_phase1(const float* __restrict__ pred,
               const int*   __restrict__ amask,
               const int*   __restrict__ labels,
               const float* __restrict__ startv,
               const float* __restrict__ endv,
               const float* __restrict__ trans)
{
    const int wib  = threadIdx.x >> 5;
    const int lane = threadIdx.x & 31;

    if (blockIdx.x >= (Bn * NCH) / 4) {
        // ------- Numerator: one warp per batch ------------------------------
        const int b = ((int)blockIdx.x - (Bn * NCH) / 4) * 4 + wib;
        const float* em = pred + (size_t)b * Sn * Tn;
        const int* lab = labels + (size_t)b * Sn;
        const int* am  = amask  + (size_t)b * Sn;
        float sum = 0.f;
        int   msum = 0;
        for (int t = lane; t < Sn; t += 32) {
            const int mt = am[t];
            msum += mt;
            const int tg = lab[t];
            if (t == 0) {
                sum += startv[tg] + em[tg];
            } else {
                const int tp = lab[t - 1];
                sum += (trans[tp * Tn + tg] + em[(size_t)t * Tn + tg]) * (float)mt;
            }
        }
        #pragma unroll
        for (int off = 16; off; off >>= 1) {
            sum  += __shfl_xor_sync(FULLMASK, sum, off);
            msum += __shfl_xor_sync(FULLMASK, msum, off);
        }
        if (lane == 0) {
            const int se = msum - 1;
            const int lt = lab[se];
            g_num[b] = sum + endv[lt];
        }
        return;
    }

    const int gw = (blockIdx.x << 2) | wib;       // 0 .. Bn*NCH-1
    const int b = gw >> 6;
    const int c = gw & 63;
    const int n = (c == 63) ? 31 : 32;            // idx max = 2046

    __shared__ __align__(16) uint32_t S4[4][8 * Tn];
    uint32_t* Sw = S4[wib];
    const uint32_t* hsrc = g_hist4 + ((size_t)b * NR + 8 * c) * Tn;
    for (int i = lane; i < 8 * Tn; i += 32) Sw[i] = hsrc[i];
    __syncwarp();

    int tag = lane;
    #pragma unroll
    for (int k = 31; k >= 0; --k) {
        if (k < n) {
            const uint32_t w = Sw[(k >> 2) * Tn + tag];
            tag = (int)((w >> ((k & 3) * 8)) & 255u);
        }
    }
    g_map[b][c][lane] = (unsigned char)tag;
}

// ---------------------------------------------------------------------------
// bt_phase3: blocks 0..4095 decode one chunk each (entry tag derived locally
// by composing the suffix of chunk maps); block 4096 computes the loss.
// ---------------------------------------------------------------------------
__global__ __launch_bounds__(128)
void bt_phase3(float* __restrict__ out)
{
    if (blockIdx.x == (Bn * NCH) / 4) {
        // ------- Loss: -mean(num - den) -------------------------------------
        __shared__ float red[128];
        const int t = threadIdx.x;
        red[t] = (g_num[t] - g_den[t]) + (g_num[t + 128] - g_den[t + 128]);
        __syncthreads();
        #pragma unroll
        for (int off = 64; off; off >>= 1) {
            if (t < off) red[t] += red[t + off];
            __syncthreads();
        }
        if (t == 0) out[(size_t)Bn * Sn] = -(red[0] / (float)Bn);
        return;
    }

    const int wib  = threadIdx.x >> 5;
    const int lane = threadIdx.x & 31;
    const int gw = (blockIdx.x << 2) | wib;
    const int b = gw >> 6;
    const int c = gw & 63;
    const int lo = c * 32;
    const int n = (c == 63) ? 31 : 32;

    __shared__ __align__(16) uint32_t S4[4][8 * Tn];
    __shared__ __align__(16) uint32_t Mw[4][(NCH * Tn) / 4];

    // stage this chunk's packed hist words
    uint32_t* Sw = S4[wib];
    const uint32_t* hsrc = g_hist4 + ((size_t)b * NR + 8 * c) * Tn;
    for (int i = lane; i < 8 * Tn; i += 32) Sw[i] = hsrc[i];

    // stage suffix maps c..63 (rows of 32 bytes = 8 words each)
    uint32_t* Mq = Mw[wib];
    const int nrows = NCH - c;
    const uint32_t* msrc = (const uint32_t*)&g_map[b][c][0];
    for (int i = lane; i < nrows * 8; i += 32) Mq[i] = msrc[i];
    __syncwarp();

    // entry tag: compose maps 63 -> c+1 starting from g_last (all lanes, bcast)
    int e = g_last[b];
    const unsigned char* Mb = (const unsigned char*)Mq;
    for (int cc = 63; cc > c; --cc)
        e = Mb[(cc - c) * Tn + e];

    // decode: chase through the chunk; lane L captures position lo+L
    int tag = e;
    int cur = 0;
    #pragma unroll
    for (int k = 31; k >= 0; --k) {
        if (k < n) {
            const uint32_t w = Sw[(k >> 2) * Tn + tag];
            tag = (int)((w >> ((k & 3) * 8)) & 255u);
            if (k == lane) cur = tag;
        }
    }
    if (lane < n) out[(size_t)b * Sn + lo + lane] = (float)cur;
    if (c == 63 && lane == 31) out[(size_t)b * Sn + (Sn - 1)] = (float)g_last[b];
}

extern "C" void kernel_launch(void* const* d_in, const int* in_sizes, int n_in,
                              void* d_out, int out_size)
{
    const float* pred   = (const float*)d_in[0];
    const int*   amask  = (const int*)  d_in[1];
    const int*   labels = (const int*)  d_in[2];
    const float* startv = (const float*)d_in[3];
    const float* endv   = (const float*)d_in[4];
    const float* trans  = (const float*)d_in[5];
    float* out = (float*)d_out;

    crf_main_kernel<<<128, 128>>>(pred, amask, startv, endv, trans);
    bt_phase1<<<(Bn * NCH) / 4 + Bn / 4, 128>>>(pred, amask, labels, startv, endv, trans);
    bt_phase3<<<(Bn * NCH) / 4 + 1, 128>>>(out);
}